// round 11
// baseline (speedup 1.0000x reference)
#include <cuda_runtime.h>
#include <cuda_fp16.h>
#include <cstdint>
#include <cstddef>

// ---------------------------------------------------------------------------
// RankOneMoE via fp16 mma.sync.m16n8k16 (fp32 accumulate). fp16 mantissa ==
// tf32 mantissa -> rn-rounded fp16 operands give tf32-grade accuracy.
//   gw[b,ek]  = (sum_s relu(x@gw1^T+b1g))[b,:]@gw2[ek,:]^T /512 + b2g[ek]
//   h         = relu([x | (x@SVH1^T)*gw] @ [W1^T ; U1] + b1m)
//   out       = [h | (h@SVH2^T)*gw] @ [W2^T ; U2] + b2m
// Per-16 k-pair permutation -> fragment = 1 LDS.64; rows padded to 96B.
// R11: fc tiles BM128xBN256 with 512 threads (16 warps of 32x64) at 1 CTA/SM
//      -> halved L2 operand traffic while keeping 16 warps/SM; fc2 direct
//      again (split-K round-trip removed); router fused-mean kept.
// ---------------------------------------------------------------------------

#define BQ   16
#define SQ   512
#define HQ   768
#define FQ   3072
#define EQ   8
#define EKQ  128
#define G1Q  256
#define NTOK (BQ*SQ)      // 8192
#define LAMBDA 0.2f

// ---- scratch layout (float units; fp16 buffers use half the floats) ----
#define OFF_XC    0                         // 8192*768 h
#define OFF_WG1   3145728                   // 256*768 h
#define OFF_SVH1  3244032                   // 128*768 h
#define OFF_W1    3293184                   // 3072*768 h
#define OFF_U1T   4472832                   // 3072*128 h
#define OFF_SVH2  4669440                   // 128*3072 h
#define OFF_W2    4866048                   // 768*3072 h
#define OFF_U2T   6045696                   // 768*128 h
#define OFF_T1S   6094848                   // 8192*128 h
#define OFF_T2S   6619136                   // 8192*128 h
#define OFF_H     7143424                   // 8192*3072 h
#define OFF_T1P   19726336                  // 2*8192*128 f
#define OFF_T2P   21823488                  // 4*8192*128 f
#define OFF_P8    26017792                  // 128*256 f
#define OFF_GWV   26050560                  // 16*128 f
#define OFF_B1M   26052608                  // 3072 f
#define OFF_B2M   26055680                  // 768 f
#define SCRATCH_FLOATS 26056448

static __device__ __align__(256) float g_scratch[SCRATCH_FLOATS];

// ---------------------------- helpers --------------------------------------
__device__ __forceinline__ uint32_t s2u(const void* p) {
    uint32_t a;
    asm("{ .reg .u64 t; cvta.to.shared.u64 t, %1; cvt.u32.u64 %0, t; }" : "=r"(a) : "l"(p));
    return a;
}
// position of original k (0..15) inside the permuted 16-group
__device__ __forceinline__ int ipos16(int k) {
    return (k & 1) + ((k >> 3) & 1) * 2 + (k & 6) * 2;
}
__device__ __forceinline__ void mma16(float* c,
                                      uint32_t a0, uint32_t a1, uint32_t a2, uint32_t a3,
                                      uint32_t b0, uint32_t b1) {
    asm volatile(
        "mma.sync.aligned.m16n8k16.row.col.f32.f16.f16.f32 "
        "{%0,%1,%2,%3},{%4,%5,%6,%7},{%8,%9},{%0,%1,%2,%3};\n"
        : "+f"(c[0]), "+f"(c[1]), "+f"(c[2]), "+f"(c[3])
        : "r"(a0), "r"(a1), "r"(a2), "r"(a3), "r"(b0), "r"(b1));
}

// ---------------------------- pack kernels ---------------------------------
struct PackJobs {
    const float* src[6];
    float*       dst[6];   // fp16 storage viewed as float words
    int          ngroups[6];
};

// fp32 -> fp16(rn) with per-16 k-pair permutation [0,1,8,9,2,3,10,11,...]
__global__ void k_pack6(PackJobs J) {
    const int job = blockIdx.y;
    const int g = blockIdx.x * blockDim.x + threadIdx.x;
    if (g >= J.ngroups[job]) return;
    const float4* s = reinterpret_cast<const float4*>(J.src[job]) + (size_t)g * 4;
    float4 v0 = s[0], v1 = s[1], v2 = s[2], v3 = s[3];
    __half2 h[8];
    h[0] = __floats2half2_rn(v0.x, v0.y);
    h[1] = __floats2half2_rn(v2.x, v2.y);
    h[2] = __floats2half2_rn(v0.z, v0.w);
    h[3] = __floats2half2_rn(v2.z, v2.w);
    h[4] = __floats2half2_rn(v1.x, v1.y);
    h[5] = __floats2half2_rn(v3.x, v3.y);
    h[6] = __floats2half2_rn(v1.z, v1.w);
    h[7] = __floats2half2_rn(v3.z, v3.w);
    float4* d = reinterpret_cast<float4*>(reinterpret_cast<__half*>(J.dst[job]) + (size_t)g * 16);
    d[0] = *reinterpret_cast<float4*>(&h[0]);
    d[1] = *reinterpret_cast<float4*>(&h[4]);
}

// transpose src[128, Ncols] f32 -> dst[Ncols, 128] fp16 permuted
__global__ void k_tr_ilv(const float* __restrict__ S_, __half* __restrict__ Dst, int Ncols) {
    __shared__ float t[32][33];
    const int nx = blockIdx.x * 32, my = blockIdx.y * 32;
    const int x = threadIdx.x, y = threadIdx.y;
    #pragma unroll
    for (int i = 0; i < 32; i += 8)
        t[y + i][x] = S_[(size_t)(my + y + i) * Ncols + nx + x];
    __syncthreads();
    #pragma unroll
    for (int i = 0; i < 32; i += 8) {
        const int r = my + x;
        const int pos = (r & ~15) + ipos16(r & 15);
        Dst[(size_t)(nx + y + i) * 128 + pos] = __float2half_rn(t[x][y + i]);
    }
}

__global__ void k_prep(const float* __restrict__ b1, const float* __restrict__ tb1,
                       const float* __restrict__ b2, const float* __restrict__ tb2,
                       float* __restrict__ b1m, float* __restrict__ b2m) {
    int i = blockIdx.x * blockDim.x + threadIdx.x;
    if (i < FQ) {
        float s = 0.f;
        #pragma unroll
        for (int e = 0; e < EQ; ++e) s += tb1[e * FQ + i];
        b1m[i] = b1[i] + LAMBDA * s;
    }
    if (i < HQ) {
        float s = 0.f;
        #pragma unroll
        for (int e = 0; e < EQ; ++e) s += tb2[e * HQ + i];
        b2m[i] = b2[i] + LAMBDA * s;
    }
}

// gw[b,ek] = dot(P[b,:], w2[ek,:]) / 512 + gb2[ek]   (P8: [128 chunks][256])
__global__ void k_gwfin(const float* __restrict__ P8, const float* __restrict__ w2,
                        const float* __restrict__ gb2, float* __restrict__ gw) {
    __shared__ float Ps[G1Q];
    int b = blockIdx.x, t = threadIdx.x;   // 128 threads
    #pragma unroll
    for (int half = 0; half < 2; ++half) {
        int col = t + half * 128;
        float a = 0.f;
        #pragma unroll
        for (int ch = 0; ch < 8; ++ch) a += P8[(b * 8 + ch) * G1Q + col];
        Ps[col] = a;
    }
    __syncthreads();
    const float* w = w2 + (size_t)t * G1Q;
    float a = 0.f;
    #pragma unroll 8
    for (int g = 0; g < G1Q; ++g) a += w[g] * Ps[g];
    gw[b * EKQ + t] = a * (1.0f / (float)SQ) + gb2[t];
}

// split-K reduce: sum KS partials, scale by gw, convert to fp16 permuted
template<int KS>
__global__ void k_red(const float* __restrict__ tp, const float* __restrict__ gwv,
                      __half* __restrict__ ts) {
    const int idx = blockIdx.x * 256 + threadIdx.x;   // over NTOK*64 pairs
    const int r = idx >> 6, c = (idx & 63) * 2;
    float v0 = tp[(size_t)r * EKQ + c];
    float v1 = tp[(size_t)r * EKQ + c + 1];
    #pragma unroll
    for (int z = 1; z < KS; ++z) {
        v0 += tp[(size_t)z * NTOK * EKQ + (size_t)r * EKQ + c];
        v1 += tp[(size_t)z * NTOK * EKQ + (size_t)r * EKQ + c + 1];
    }
    const int gb = (r >> 9) << 7;
    v0 *= gwv[gb + c]; v1 *= gwv[gb + c + 1];
    const int pos = (c & ~15) + ipos16(c & 15);
    *reinterpret_cast<__half2*>(ts + (size_t)r * EKQ + pos) = __floats2half2_rn(v0, v1);
}

// ---------------------------------------------------------------------------
// Pipelined fp16 mma.sync GEMM. BK=32 per stage, STAGES-deep cp.async.
//   D = epi( A1[M,K1] @ B1[N,K1]^T (+ A2[M,K2] @ B2[N,K2]^T) )
//   EPI: 0=none, 1=relu, 3=router (relu + column-sum over BM rows -> aux).
//   OUTH: fp16 permuted output. SPLITK: z picks kspan window of K1.
// ---------------------------------------------------------------------------
template<int BM, int BN, int WM, int WN, int STAGES, int EPI,
         bool HAS2, bool HAS_BIAS, bool OUTH, bool SPLITK, int OCC>
__global__ void __launch_bounds__(WM * WN * 32, OCC)
k_mma(const __half* __restrict__ A1, const __half* __restrict__ B1, int K1,
      const __half* __restrict__ A2, const __half* __restrict__ B2, int K2,
      const float* __restrict__ bias, float* __restrict__ aux,
      void* __restrict__ Dv, int N, int kspan)
{
    constexpr int THREADS = WM * WN * 32;
    constexpr int WTM = BM / WM, WTN = BN / WN;
    constexpr int MT = WTM / 16, NT = WTN / 8;
    constexpr int RB = 96;                        // padded row bytes (64B data)
    constexpr int STGB = (BM + BN) * RB;
    constexpr int AIT = (BM * 4) / THREADS;
    constexpr int BIT = (BN * 4) / THREADS;

    extern __shared__ char sm[];
    const uint32_t smb = s2u(sm);

    const int tid = threadIdx.x;
    const int wid = tid >> 5, lane = tid & 31;
    const int gid = lane >> 2, tig = lane & 3;
    const int wm = (wid / WN) * WTM;
    const int wn = (wid % WN) * WTN;
    const int bM = blockIdx.y * BM;
    const int bN = blockIdx.x * BN;
    const int kbase = SPLITK ? blockIdx.z * kspan : 0;
    const int T1S = SPLITK ? (kspan >> 5) : (K1 >> 5);
    const bool tail = HAS2 && (!SPLITK || blockIdx.z == gridDim.z - 1);
    const int TS = T1S + (tail ? (K2 >> 5) : 0);

    float acc[MT][NT][4];
    #pragma unroll
    for (int mi = 0; mi < MT; ++mi)
        #pragma unroll
        for (int ni = 0; ni < NT; ++ni)
            #pragma unroll
            for (int j = 0; j < 4; ++j) acc[mi][ni][j] = 0.f;

    auto issue = [&](int jj) {
        const __half* a; const __half* b; int lda, ldb, k0;
        if (!HAS2 || jj < T1S) { a = A1; lda = K1; b = B1; ldb = K1; k0 = kbase + (jj << 5); }
        else                   { a = A2; lda = K2; b = B2; ldb = K2; k0 = (jj - T1S) << 5; }
        const uint32_t sA = smb + (uint32_t)((jj % STAGES) * STGB);
        const uint32_t sB = sA + (uint32_t)BM * RB;
        #pragma unroll
        for (int i = 0; i < AIT; ++i) {
            int idx = tid + i * THREADS; int r = idx >> 2, c = idx & 3;
            const __half* src = a + (size_t)(bM + r) * lda + k0 + c * 8;
            asm volatile("cp.async.cg.shared.global [%0], [%1], 16;\n"
                         :: "r"(sA + (uint32_t)(r * RB + c * 16)), "l"(src) : "memory");
        }
        #pragma unroll
        for (int i = 0; i < BIT; ++i) {
            int idx = tid + i * THREADS; int r = idx >> 2, c = idx & 3;
            const __half* src = b + (size_t)(bN + r) * ldb + k0 + c * 8;
            asm volatile("cp.async.cg.shared.global [%0], [%1], 16;\n"
                         :: "r"(sB + (uint32_t)(r * RB + c * 16)), "l"(src) : "memory");
        }
    };

    #pragma unroll
    for (int s = 0; s < STAGES - 1; ++s) {
        issue(s);
        asm volatile("cp.async.commit_group;\n" ::: "memory");
    }

    for (int j = 0; j < TS; ++j) {
        asm volatile("cp.async.wait_group %0;\n" :: "n"(STAGES - 2) : "memory");
        __syncthreads();

        const char* sst = sm + (j % STAGES) * STGB;
        const char* sA = sst;
        const char* sB = sst + BM * RB;

        #pragma unroll
        for (int g = 0; g < 2; ++g) {
            uint2 fb[NT];
            #pragma unroll
            for (int ni = 0; ni < NT; ++ni)
                fb[ni] = *reinterpret_cast<const uint2*>(
                    sB + (wn + ni * 8 + gid) * RB + g * 32 + tig * 8);

            if (g == 0) {
                if (j + STAGES - 1 < TS) issue(j + STAGES - 1);
                asm volatile("cp.async.commit_group;\n" ::: "memory");
            }

            #pragma unroll
            for (int mi = 0; mi < MT; ++mi) {
                const char* ra = sA + (wm + mi * 16 + gid) * RB + g * 32 + tig * 8;
                const uint2 fa0 = *reinterpret_cast<const uint2*>(ra);
                const uint2 fa1 = *reinterpret_cast<const uint2*>(ra + 8 * RB);
                #pragma unroll
                for (int ni = 0; ni < NT; ++ni)
                    mma16(acc[mi][ni], fa0.x, fa1.x, fa0.y, fa1.y,
                          fb[ni].x, fb[ni].y);
            }
        }
    }

    if (EPI == 3) {
        // router: aux[blockIdx.y][bN + col] = sum_rows relu(acc + bias)
        float part[NT][2];
        #pragma unroll
        for (int ni = 0; ni < NT; ++ni) { part[ni][0] = 0.f; part[ni][1] = 0.f; }
        #pragma unroll
        for (int ni = 0; ni < NT; ++ni) {
            const int cl = wn + ni * 8 + tig * 2;
            const float bb0 = bias[bN + cl], bb1 = bias[bN + cl + 1];
            #pragma unroll
            for (int mi = 0; mi < MT; ++mi)
                #pragma unroll
                for (int h = 0; h < 2; ++h) {
                    part[ni][0] += fmaxf(acc[mi][ni][2 * h + 0] + bb0, 0.f);
                    part[ni][1] += fmaxf(acc[mi][ni][2 * h + 1] + bb1, 0.f);
                }
        }
        #pragma unroll
        for (int ni = 0; ni < NT; ++ni)
            #pragma unroll
            for (int j2 = 0; j2 < 2; ++j2) {
                float v = part[ni][j2];
                v += __shfl_xor_sync(0xffffffffu, v, 4);
                v += __shfl_xor_sync(0xffffffffu, v, 8);
                v += __shfl_xor_sync(0xffffffffu, v, 16);
                part[ni][j2] = v;                        // valid in lanes 0-3
            }
        asm volatile("cp.async.wait_group 0;\n" ::: "memory");
        __syncthreads();
        float* red = reinterpret_cast<float*>(sm);       // reuse stage smem
        if (tid < BN) red[tid] = 0.f;
        __syncthreads();
        const int wrow = wid / WN;                       // WM == 2 assumed
        if (wrow == 0 && lane < 4) {
            #pragma unroll
            for (int ni = 0; ni < NT; ++ni) {
                red[wn + ni * 8 + lane * 2]     = part[ni][0];
                red[wn + ni * 8 + lane * 2 + 1] = part[ni][1];
            }
        }
        __syncthreads();
        if (wrow == 1 && lane < 4) {
            #pragma unroll
            for (int ni = 0; ni < NT; ++ni) {
                red[wn + ni * 8 + lane * 2]     += part[ni][0];
                red[wn + ni * 8 + lane * 2 + 1] += part[ni][1];
            }
        }
        __syncthreads();
        if (tid < BN)
            aux[(size_t)blockIdx.y * G1Q + bN + tid] = red[tid];
        return;
    }

    // normal epilogue
    float* Df = reinterpret_cast<float*>(Dv)
              + (SPLITK ? (size_t)blockIdx.z * NTOK * N : 0);
    __half* Dh = reinterpret_cast<__half*>(Dv);
    #pragma unroll
    for (int mi = 0; mi < MT; ++mi) {
        const int r0 = bM + wm + mi * 16 + gid;
        #pragma unroll
        for (int ni = 0; ni < NT; ++ni) {
            const int cl = wn + ni * 8 + tig * 2;
            const int c  = bN + cl;
            const float bb0 = HAS_BIAS ? bias[c] : 0.f;
            const float bb1 = HAS_BIAS ? bias[c + 1] : 0.f;
            #pragma unroll
            for (int h = 0; h < 2; ++h) {
                const int r = r0 + h * 8;
                float v0 = acc[mi][ni][2 * h + 0] + bb0;
                float v1 = acc[mi][ni][2 * h + 1] + bb1;
                if (EPI == 1) { v0 = fmaxf(v0, 0.f); v1 = fmaxf(v1, 0.f); }
                if (OUTH) {
                    const int pos = (c & ~15) + ipos16(c & 15);
                    *reinterpret_cast<__half2*>(Dh + (size_t)r * N + pos) =
                        __floats2half2_rn(v0, v1);
                } else {
                    *reinterpret_cast<float2*>(Df + (size_t)r * N + c) = make_float2(v0, v1);
                }
            }
        }
    }
}

// ---------------------------------------------------------------------------
extern "C" void kernel_launch(void* const* d_in, const int* in_sizes, int n_in,
                              void* d_out, int out_size) {
    const float* x       = (const float*)d_in[0];
    const float* gate_w1 = (const float*)d_in[1];
    const float* gate_b1 = (const float*)d_in[2];
    const float* gate_w2 = (const float*)d_in[3];
    const float* gate_b2 = (const float*)d_in[4];
    const float* W1      = (const float*)d_in[5];
    const float* b1      = (const float*)d_in[6];
    const float* W2      = (const float*)d_in[7];
    const float* b2      = (const float*)d_in[8];
    const float* U1      = (const float*)d_in[9];
    const float* SVH1    = (const float*)d_in[10];
    const float* U2      = (const float*)d_in[11];
    const float* SVH2    = (const float*)d_in[12];
    const float* TB1     = (const float*)d_in[13];
    const float* TB2     = (const float*)d_in[14];
    float* out = (float*)d_out;

    float* S = nullptr;
    cudaGetSymbolAddress((void**)&S, g_scratch);
    __half* xc    = (__half*)(S + OFF_XC);
    __half* wg1c  = (__half*)(S + OFF_WG1);
    __half* svh1c = (__half*)(S + OFF_SVH1);
    __half* w1c   = (__half*)(S + OFF_W1);
    __half* u1t   = (__half*)(S + OFF_U1T);
    __half* svh2c = (__half*)(S + OFF_SVH2);
    __half* w2c   = (__half*)(S + OFF_W2);
    __half* u2t   = (__half*)(S + OFF_U2T);
    __half* t1s   = (__half*)(S + OFF_T1S);
    __half* t2s   = (__half*)(S + OFF_T2S);
    __half* hbuf  = (__half*)(S + OFF_H);
    float* t1p   = S + OFF_T1P;
    float* t2p   = S + OFF_T2P;
    float* P8    = S + OFF_P8;
    float* gwv   = S + OFF_GWV;
    float* b1m   = S + OFF_B1M;
    float* b2m   = S + OFF_B2M;

    // router: BM64 BN128, 8 warps (2x4) 32x32, 4 stages, fused mean -> P8
    auto kr = k_mma<64, 128, 2, 4, 4, 3, false, true, false, false, 2>;
    // t partial GEMMs: BM64 BN128, split-K, fp32 raw partials
    auto kt = k_mma<64, 128, 2, 4, 4, 0, false, false, false, true, 2>;
    // fc1: BM128 BN256, 16 warps (4x4) of 32x64, 1 CTA/SM, fp16 ILV out
    auto k1 = k_mma<128, 256, 4, 4, 4, 1, true, true, true, false, 1>;
    // fc2: same shape, direct (bias + U2 tail in-kernel), fp32 out
    auto k2 = k_mma<128, 256, 4, 4, 4, 0, true, true, false, false, 1>;

    const int SM_RT = 4 * (64 + 128) * 96;      // 73728
    const int SM_F  = 4 * (128 + 256) * 96;     // 147456
    cudaFuncSetAttribute((const void*)kr, cudaFuncAttributeMaxDynamicSharedMemorySize, SM_RT);
    cudaFuncSetAttribute((const void*)kt, cudaFuncAttributeMaxDynamicSharedMemorySize, SM_RT);
    cudaFuncSetAttribute((const void*)k1, cudaFuncAttributeMaxDynamicSharedMemorySize, SM_F);
    cudaFuncSetAttribute((const void*)k2, cudaFuncAttributeMaxDynamicSharedMemorySize, SM_F);

    // 0: all fp32->fp16(rn) packs with k-permutation, one launch
    PackJobs J;
    J.src[0] = x;       J.dst[0] = (float*)xc;    J.ngroups[0] = NTOK * HQ / 16;
    J.src[1] = gate_w1; J.dst[1] = (float*)wg1c;  J.ngroups[1] = G1Q * HQ / 16;
    J.src[2] = SVH1;    J.dst[2] = (float*)svh1c; J.ngroups[2] = EKQ * HQ / 16;
    J.src[3] = W1;      J.dst[3] = (float*)w1c;   J.ngroups[3] = FQ * HQ / 16;
    J.src[4] = SVH2;    J.dst[4] = (float*)svh2c; J.ngroups[4] = EKQ * FQ / 16;
    J.src[5] = W2;      J.dst[5] = (float*)w2c;   J.ngroups[5] = HQ * FQ / 16;
    k_pack6<<<dim3((NTOK * HQ / 16 + 255) / 256, 6), 256>>>(J);

    // 1: router, fused column-mean -> P8 [128][256]
    kr<<<dim3(G1Q / 128, NTOK / 64), 256, SM_RT>>>(
        xc, wg1c, HQ, nullptr, nullptr, 0, gate_b1, P8, nullptr, G1Q, 0);

    // 2: gw
    k_gwfin<<<BQ, 128>>>(P8, gate_w2, gate_b2, gwv);

    // 3: t1 partials = x @ SVH1^T, K split 2x384
    kt<<<dim3(1, NTOK / 64, 2), 256, SM_RT>>>(
        xc, svh1c, HQ, nullptr, nullptr, 0, nullptr, nullptr, t1p, EKQ, HQ / 2);

    // 4: t1s = fp16(sum_z t1p * gw), permuted
    k_red<2><<<NTOK * 64 / 256, 256>>>(t1p, gwv, t1s);

    // 5,6: transposed low-rank factors -> fp16 permuted
    k_tr_ilv<<<dim3(FQ / 32, 4), dim3(32, 8)>>>(U1, u1t, FQ);
    k_tr_ilv<<<dim3(HQ / 32, 4), dim3(32, 8)>>>(U2, u2t, HQ);

    // 7: merged biases (fp32)
    k_prep<<<(FQ + 255) / 256, 256>>>(b1, TB1, b2, TB2, b1m, b2m);

    // 8: h = fp16(relu(x @ W1^T + t1s @ U1 + b1m))   [8192,3072]
    k1<<<dim3(FQ / 256, NTOK / 128), 512, SM_F>>>(
        xc, w1c, HQ, t1s, u1t, EKQ, b1m, nullptr, hbuf, FQ, 0);

    // 9: t2 partials = h @ SVH2^T, K split 4x768
    kt<<<dim3(1, NTOK / 64, 4), 256, SM_RT>>>(
        hbuf, svh2c, FQ, nullptr, nullptr, 0, nullptr, nullptr, t2p, EKQ, FQ / 4);

    // 10: t2s = fp16(sum_z t2p * gw), permuted
    k_red<4><<<NTOK * 64 / 256, 256>>>(t2p, gwv, t2s);

    // 11: out = h @ W2^T + t2s @ U2 + b2m   [8192,768] fp32
    k2<<<dim3(HQ / 256, NTOK / 128), 512, SM_F>>>(
        hbuf, w2c, FQ, t2s, u2t, EKQ, b2m, nullptr, out, HQ, 0);
}

// round 12
// speedup vs baseline: 1.1606x; 1.1606x over previous
#include <cuda_runtime.h>
#include <cuda_fp16.h>
#include <cstdint>
#include <cstddef>

// ---------------------------------------------------------------------------
// RankOneMoE via fp16 mma.sync.m16n8k16 (fp32 accumulate). fp16 mantissa ==
// tf32 mantissa -> rn-rounded fp16 operands give tf32-grade accuracy.
//   gw[b,ek]  = (sum_s relu(x@gw1^T+b1g))[b,:]@gw2[ek,:]^T /512 + b2g[ek]
//   h         = relu([x | (x@SVH1^T)*gw] @ [W1^T ; U1] + b1m)
//   out       = [h | (h@SVH2^T)*gw] @ [W2^T ; U2] + b2m
// Per-16 k-pair permutation -> fragment = 1 LDS.64; rows padded to 96B.
// R12: REVERT fc to the measured-best R9 shape (BM128xBN128, 8 warps 64x32,
//      2 CTA/SM — cross-CTA overlap is load-bearing; BN256/1-CTA regressed
//      twice). Keep R10's router fused-mean (sumG1b + G1 round-trip removed).
// ---------------------------------------------------------------------------

#define BQ   16
#define SQ   512
#define HQ   768
#define FQ   3072
#define EQ   8
#define EKQ  128
#define G1Q  256
#define NTOK (BQ*SQ)      // 8192
#define LAMBDA 0.2f

// ---- scratch layout (float units; fp16 buffers use half the floats) ----
#define OFF_XC    0                         // 8192*768 h
#define OFF_WG1   3145728                   // 256*768 h
#define OFF_SVH1  3244032                   // 128*768 h
#define OFF_W1    3293184                   // 3072*768 h
#define OFF_U1T   4472832                   // 3072*128 h
#define OFF_SVH2  4669440                   // 128*3072 h
#define OFF_W2    4866048                   // 768*3072 h
#define OFF_U2T   6045696                   // 768*128 h
#define OFF_T1S   6094848                   // 8192*128 h
#define OFF_T2S   6619136                   // 8192*128 h
#define OFF_H     7143424                   // 8192*3072 h
#define OFF_T1P   19726336                  // 2*8192*128 f
#define OFF_T2P   21823488                  // 4*8192*128 f
#define OFF_P8    26017792                  // 128*256 f
#define OFF_GWV   26050560                  // 16*128 f
#define OFF_B1M   26052608                  // 3072 f
#define OFF_B2M   26055680                  // 768 f
#define SCRATCH_FLOATS 26056448

static __device__ __align__(256) float g_scratch[SCRATCH_FLOATS];

// ---------------------------- helpers --------------------------------------
__device__ __forceinline__ uint32_t s2u(const void* p) {
    uint32_t a;
    asm("{ .reg .u64 t; cvta.to.shared.u64 t, %1; cvt.u32.u64 %0, t; }" : "=r"(a) : "l"(p));
    return a;
}
// position of original k (0..15) inside the permuted 16-group
__device__ __forceinline__ int ipos16(int k) {
    return (k & 1) + ((k >> 3) & 1) * 2 + (k & 6) * 2;
}
__device__ __forceinline__ void mma16(float* c,
                                      uint32_t a0, uint32_t a1, uint32_t a2, uint32_t a3,
                                      uint32_t b0, uint32_t b1) {
    asm volatile(
        "mma.sync.aligned.m16n8k16.row.col.f32.f16.f16.f32 "
        "{%0,%1,%2,%3},{%4,%5,%6,%7},{%8,%9},{%0,%1,%2,%3};\n"
        : "+f"(c[0]), "+f"(c[1]), "+f"(c[2]), "+f"(c[3])
        : "r"(a0), "r"(a1), "r"(a2), "r"(a3), "r"(b0), "r"(b1));
}

// ---------------------------- pack kernels ---------------------------------
struct PackJobs {
    const float* src[6];
    float*       dst[6];   // fp16 storage viewed as float words
    int          ngroups[6];
};

// fp32 -> fp16(rn) with per-16 k-pair permutation [0,1,8,9,2,3,10,11,...]
__global__ void k_pack6(PackJobs J) {
    const int job = blockIdx.y;
    const int g = blockIdx.x * blockDim.x + threadIdx.x;
    if (g >= J.ngroups[job]) return;
    const float4* s = reinterpret_cast<const float4*>(J.src[job]) + (size_t)g * 4;
    float4 v0 = s[0], v1 = s[1], v2 = s[2], v3 = s[3];
    __half2 h[8];
    h[0] = __floats2half2_rn(v0.x, v0.y);
    h[1] = __floats2half2_rn(v2.x, v2.y);
    h[2] = __floats2half2_rn(v0.z, v0.w);
    h[3] = __floats2half2_rn(v2.z, v2.w);
    h[4] = __floats2half2_rn(v1.x, v1.y);
    h[5] = __floats2half2_rn(v3.x, v3.y);
    h[6] = __floats2half2_rn(v1.z, v1.w);
    h[7] = __floats2half2_rn(v3.z, v3.w);
    float4* d = reinterpret_cast<float4*>(reinterpret_cast<__half*>(J.dst[job]) + (size_t)g * 16);
    d[0] = *reinterpret_cast<float4*>(&h[0]);
    d[1] = *reinterpret_cast<float4*>(&h[4]);
}

// transpose src[128, Ncols] f32 -> dst[Ncols, 128] fp16 permuted
__global__ void k_tr_ilv(const float* __restrict__ S_, __half* __restrict__ Dst, int Ncols) {
    __shared__ float t[32][33];
    const int nx = blockIdx.x * 32, my = blockIdx.y * 32;
    const int x = threadIdx.x, y = threadIdx.y;
    #pragma unroll
    for (int i = 0; i < 32; i += 8)
        t[y + i][x] = S_[(size_t)(my + y + i) * Ncols + nx + x];
    __syncthreads();
    #pragma unroll
    for (int i = 0; i < 32; i += 8) {
        const int r = my + x;
        const int pos = (r & ~15) + ipos16(r & 15);
        Dst[(size_t)(nx + y + i) * 128 + pos] = __float2half_rn(t[x][y + i]);
    }
}

__global__ void k_prep(const float* __restrict__ b1, const float* __restrict__ tb1,
                       const float* __restrict__ b2, const float* __restrict__ tb2,
                       float* __restrict__ b1m, float* __restrict__ b2m) {
    int i = blockIdx.x * blockDim.x + threadIdx.x;
    if (i < FQ) {
        float s = 0.f;
        #pragma unroll
        for (int e = 0; e < EQ; ++e) s += tb1[e * FQ + i];
        b1m[i] = b1[i] + LAMBDA * s;
    }
    if (i < HQ) {
        float s = 0.f;
        #pragma unroll
        for (int e = 0; e < EQ; ++e) s += tb2[e * HQ + i];
        b2m[i] = b2[i] + LAMBDA * s;
    }
}

// gw[b,ek] = dot(P[b,:], w2[ek,:]) / 512 + gb2[ek]   (P8: [128 chunks][256])
__global__ void k_gwfin(const float* __restrict__ P8, const float* __restrict__ w2,
                        const float* __restrict__ gb2, float* __restrict__ gw) {
    __shared__ float Ps[G1Q];
    int b = blockIdx.x, t = threadIdx.x;   // 128 threads
    #pragma unroll
    for (int half = 0; half < 2; ++half) {
        int col = t + half * 128;
        float a = 0.f;
        #pragma unroll
        for (int ch = 0; ch < 8; ++ch) a += P8[(b * 8 + ch) * G1Q + col];
        Ps[col] = a;
    }
    __syncthreads();
    const float* w = w2 + (size_t)t * G1Q;
    float a = 0.f;
    #pragma unroll 8
    for (int g = 0; g < G1Q; ++g) a += w[g] * Ps[g];
    gw[b * EKQ + t] = a * (1.0f / (float)SQ) + gb2[t];
}

// split-K reduce: sum KS partials, scale by gw, convert to fp16 permuted
template<int KS>
__global__ void k_red(const float* __restrict__ tp, const float* __restrict__ gwv,
                      __half* __restrict__ ts) {
    const int idx = blockIdx.x * 256 + threadIdx.x;   // over NTOK*64 pairs
    const int r = idx >> 6, c = (idx & 63) * 2;
    float v0 = tp[(size_t)r * EKQ + c];
    float v1 = tp[(size_t)r * EKQ + c + 1];
    #pragma unroll
    for (int z = 1; z < KS; ++z) {
        v0 += tp[(size_t)z * NTOK * EKQ + (size_t)r * EKQ + c];
        v1 += tp[(size_t)z * NTOK * EKQ + (size_t)r * EKQ + c + 1];
    }
    const int gb = (r >> 9) << 7;
    v0 *= gwv[gb + c]; v1 *= gwv[gb + c + 1];
    const int pos = (c & ~15) + ipos16(c & 15);
    *reinterpret_cast<__half2*>(ts + (size_t)r * EKQ + pos) = __floats2half2_rn(v0, v1);
}

// ---------------------------------------------------------------------------
// Pipelined fp16 mma.sync GEMM. BK=32 per stage, STAGES-deep cp.async.
//   D = epi( A1[M,K1] @ B1[N,K1]^T (+ A2[M,K2] @ B2[N,K2]^T) )
//   EPI: 0=none, 1=relu, 3=router (relu + column-sum over BM rows -> aux).
//   OUTH: fp16 permuted output. SPLITK: z picks kspan window of K1.
// ---------------------------------------------------------------------------
template<int BM, int BN, int WM, int WN, int STAGES, int EPI,
         bool HAS2, bool HAS_BIAS, bool OUTH, bool SPLITK, int OCC>
__global__ void __launch_bounds__(WM * WN * 32, OCC)
k_mma(const __half* __restrict__ A1, const __half* __restrict__ B1, int K1,
      const __half* __restrict__ A2, const __half* __restrict__ B2, int K2,
      const float* __restrict__ bias, float* __restrict__ aux,
      void* __restrict__ Dv, int N, int kspan)
{
    constexpr int THREADS = WM * WN * 32;
    constexpr int WTM = BM / WM, WTN = BN / WN;
    constexpr int MT = WTM / 16, NT = WTN / 8;
    constexpr int RB = 96;                        // padded row bytes (64B data)
    constexpr int STGB = (BM + BN) * RB;
    constexpr int AIT = (BM * 4) / THREADS;
    constexpr int BIT = (BN * 4) / THREADS;

    extern __shared__ char sm[];
    const uint32_t smb = s2u(sm);

    const int tid = threadIdx.x;
    const int wid = tid >> 5, lane = tid & 31;
    const int gid = lane >> 2, tig = lane & 3;
    const int wm = (wid / WN) * WTM;
    const int wn = (wid % WN) * WTN;
    const int bM = blockIdx.y * BM;
    const int bN = blockIdx.x * BN;
    const int kbase = SPLITK ? blockIdx.z * kspan : 0;
    const int T1S = SPLITK ? (kspan >> 5) : (K1 >> 5);
    const bool tail = HAS2 && (!SPLITK || blockIdx.z == gridDim.z - 1);
    const int TS = T1S + (tail ? (K2 >> 5) : 0);

    float acc[MT][NT][4];
    #pragma unroll
    for (int mi = 0; mi < MT; ++mi)
        #pragma unroll
        for (int ni = 0; ni < NT; ++ni)
            #pragma unroll
            for (int j = 0; j < 4; ++j) acc[mi][ni][j] = 0.f;

    auto issue = [&](int jj) {
        const __half* a; const __half* b; int lda, ldb, k0;
        if (!HAS2 || jj < T1S) { a = A1; lda = K1; b = B1; ldb = K1; k0 = kbase + (jj << 5); }
        else                   { a = A2; lda = K2; b = B2; ldb = K2; k0 = (jj - T1S) << 5; }
        const uint32_t sA = smb + (uint32_t)((jj % STAGES) * STGB);
        const uint32_t sB = sA + (uint32_t)BM * RB;
        #pragma unroll
        for (int i = 0; i < AIT; ++i) {
            int idx = tid + i * THREADS; int r = idx >> 2, c = idx & 3;
            const __half* src = a + (size_t)(bM + r) * lda + k0 + c * 8;
            asm volatile("cp.async.cg.shared.global [%0], [%1], 16;\n"
                         :: "r"(sA + (uint32_t)(r * RB + c * 16)), "l"(src) : "memory");
        }
        #pragma unroll
        for (int i = 0; i < BIT; ++i) {
            int idx = tid + i * THREADS; int r = idx >> 2, c = idx & 3;
            const __half* src = b + (size_t)(bN + r) * ldb + k0 + c * 8;
            asm volatile("cp.async.cg.shared.global [%0], [%1], 16;\n"
                         :: "r"(sB + (uint32_t)(r * RB + c * 16)), "l"(src) : "memory");
        }
    };

    #pragma unroll
    for (int s = 0; s < STAGES - 1; ++s) {
        issue(s);
        asm volatile("cp.async.commit_group;\n" ::: "memory");
    }

    for (int j = 0; j < TS; ++j) {
        asm volatile("cp.async.wait_group %0;\n" :: "n"(STAGES - 2) : "memory");
        __syncthreads();

        const char* sst = sm + (j % STAGES) * STGB;
        const char* sA = sst;
        const char* sB = sst + BM * RB;

        #pragma unroll
        for (int g = 0; g < 2; ++g) {
            uint2 fb[NT];
            #pragma unroll
            for (int ni = 0; ni < NT; ++ni)
                fb[ni] = *reinterpret_cast<const uint2*>(
                    sB + (wn + ni * 8 + gid) * RB + g * 32 + tig * 8);

            if (g == 0) {
                if (j + STAGES - 1 < TS) issue(j + STAGES - 1);
                asm volatile("cp.async.commit_group;\n" ::: "memory");
            }

            #pragma unroll
            for (int mi = 0; mi < MT; ++mi) {
                const char* ra = sA + (wm + mi * 16 + gid) * RB + g * 32 + tig * 8;
                const uint2 fa0 = *reinterpret_cast<const uint2*>(ra);
                const uint2 fa1 = *reinterpret_cast<const uint2*>(ra + 8 * RB);
                #pragma unroll
                for (int ni = 0; ni < NT; ++ni)
                    mma16(acc[mi][ni], fa0.x, fa1.x, fa0.y, fa1.y,
                          fb[ni].x, fb[ni].y);
            }
        }
    }

    if (EPI == 3) {
        // router: aux[blockIdx.y][bN + col] = sum_rows relu(acc + bias)
        float part[NT][2];
        #pragma unroll
        for (int ni = 0; ni < NT; ++ni) { part[ni][0] = 0.f; part[ni][1] = 0.f; }
        #pragma unroll
        for (int ni = 0; ni < NT; ++ni) {
            const int cl = wn + ni * 8 + tig * 2;
            const float bb0 = bias[bN + cl], bb1 = bias[bN + cl + 1];
            #pragma unroll
            for (int mi = 0; mi < MT; ++mi)
                #pragma unroll
                for (int h = 0; h < 2; ++h) {
                    part[ni][0] += fmaxf(acc[mi][ni][2 * h + 0] + bb0, 0.f);
                    part[ni][1] += fmaxf(acc[mi][ni][2 * h + 1] + bb1, 0.f);
                }
        }
        #pragma unroll
        for (int ni = 0; ni < NT; ++ni)
            #pragma unroll
            for (int j2 = 0; j2 < 2; ++j2) {
                float v = part[ni][j2];
                v += __shfl_xor_sync(0xffffffffu, v, 4);
                v += __shfl_xor_sync(0xffffffffu, v, 8);
                v += __shfl_xor_sync(0xffffffffu, v, 16);
                part[ni][j2] = v;                        // valid in lanes 0-3
            }
        asm volatile("cp.async.wait_group 0;\n" ::: "memory");
        __syncthreads();
        float* red = reinterpret_cast<float*>(sm);       // reuse stage smem
        if (tid < BN) red[tid] = 0.f;
        __syncthreads();
        const int wrow = wid / WN;                       // WM == 2 assumed
        if (wrow == 0 && lane < 4) {
            #pragma unroll
            for (int ni = 0; ni < NT; ++ni) {
                red[wn + ni * 8 + lane * 2]     = part[ni][0];
                red[wn + ni * 8 + lane * 2 + 1] = part[ni][1];
            }
        }
        __syncthreads();
        if (wrow == 1 && lane < 4) {
            #pragma unroll
            for (int ni = 0; ni < NT; ++ni) {
                red[wn + ni * 8 + lane * 2]     += part[ni][0];
                red[wn + ni * 8 + lane * 2 + 1] += part[ni][1];
            }
        }
        __syncthreads();
        if (tid < BN)
            aux[(size_t)blockIdx.y * G1Q + bN + tid] = red[tid];
        return;
    }

    // normal epilogue
    float* Df = reinterpret_cast<float*>(Dv)
              + (SPLITK ? (size_t)blockIdx.z * NTOK * N : 0);
    __half* Dh = reinterpret_cast<__half*>(Dv);
    #pragma unroll
    for (int mi = 0; mi < MT; ++mi) {
        const int r0 = bM + wm + mi * 16 + gid;
        #pragma unroll
        for (int ni = 0; ni < NT; ++ni) {
            const int cl = wn + ni * 8 + tig * 2;
            const int c  = bN + cl;
            const float bb0 = HAS_BIAS ? bias[c] : 0.f;
            const float bb1 = HAS_BIAS ? bias[c + 1] : 0.f;
            #pragma unroll
            for (int h = 0; h < 2; ++h) {
                const int r = r0 + h * 8;
                float v0 = acc[mi][ni][2 * h + 0] + bb0;
                float v1 = acc[mi][ni][2 * h + 1] + bb1;
                if (EPI == 1) { v0 = fmaxf(v0, 0.f); v1 = fmaxf(v1, 0.f); }
                if (OUTH) {
                    const int pos = (c & ~15) + ipos16(c & 15);
                    *reinterpret_cast<__half2*>(Dh + (size_t)r * N + pos) =
                        __floats2half2_rn(v0, v1);
                } else {
                    *reinterpret_cast<float2*>(Df + (size_t)r * N + c) = make_float2(v0, v1);
                }
            }
        }
    }
}

// ---------------------------------------------------------------------------
extern "C" void kernel_launch(void* const* d_in, const int* in_sizes, int n_in,
                              void* d_out, int out_size) {
    const float* x       = (const float*)d_in[0];
    const float* gate_w1 = (const float*)d_in[1];
    const float* gate_b1 = (const float*)d_in[2];
    const float* gate_w2 = (const float*)d_in[3];
    const float* gate_b2 = (const float*)d_in[4];
    const float* W1      = (const float*)d_in[5];
    const float* b1      = (const float*)d_in[6];
    const float* W2      = (const float*)d_in[7];
    const float* b2      = (const float*)d_in[8];
    const float* U1      = (const float*)d_in[9];
    const float* SVH1    = (const float*)d_in[10];
    const float* U2      = (const float*)d_in[11];
    const float* SVH2    = (const float*)d_in[12];
    const float* TB1     = (const float*)d_in[13];
    const float* TB2     = (const float*)d_in[14];
    float* out = (float*)d_out;

    float* S = nullptr;
    cudaGetSymbolAddress((void**)&S, g_scratch);
    __half* xc    = (__half*)(S + OFF_XC);
    __half* wg1c  = (__half*)(S + OFF_WG1);
    __half* svh1c = (__half*)(S + OFF_SVH1);
    __half* w1c   = (__half*)(S + OFF_W1);
    __half* u1t   = (__half*)(S + OFF_U1T);
    __half* svh2c = (__half*)(S + OFF_SVH2);
    __half* w2c   = (__half*)(S + OFF_W2);
    __half* u2t   = (__half*)(S + OFF_U2T);
    __half* t1s   = (__half*)(S + OFF_T1S);
    __half* t2s   = (__half*)(S + OFF_T2S);
    __half* hbuf  = (__half*)(S + OFF_H);
    float* t1p   = S + OFF_T1P;
    float* t2p   = S + OFF_T2P;
    float* P8    = S + OFF_P8;
    float* gwv   = S + OFF_GWV;
    float* b1m   = S + OFF_B1M;
    float* b2m   = S + OFF_B2M;

    // router: BM64 BN128, 8 warps (2x4) 32x32, 4 stages, fused mean -> P8
    auto kr = k_mma<64, 128, 2, 4, 4, 3, false, true, false, false, 2>;
    // t partial GEMMs: BM64 BN128, split-K, fp32 raw partials
    auto kt = k_mma<64, 128, 2, 4, 4, 0, false, false, false, true, 2>;
    // fc1: BM128 BN128, 8 warps (2x4) of 64x32, 2 CTA/SM, fp16 ILV out  (R9)
    auto k1 = k_mma<128, 128, 2, 4, 4, 1, true, true, true, false, 2>;
    // fc2: same shape, direct (bias + U2 tail in-kernel), fp32 out      (R9)
    auto k2 = k_mma<128, 128, 2, 4, 4, 0, true, true, false, false, 2>;

    const int SM_RT = 4 * (64 + 128) * 96;      // 73728
    const int SM_F  = 4 * (128 + 128) * 96;     // 98304
    cudaFuncSetAttribute((const void*)kr, cudaFuncAttributeMaxDynamicSharedMemorySize, SM_RT);
    cudaFuncSetAttribute((const void*)kt, cudaFuncAttributeMaxDynamicSharedMemorySize, SM_RT);
    cudaFuncSetAttribute((const void*)k1, cudaFuncAttributeMaxDynamicSharedMemorySize, SM_F);
    cudaFuncSetAttribute((const void*)k2, cudaFuncAttributeMaxDynamicSharedMemorySize, SM_F);

    // 0: all fp32->fp16(rn) packs with k-permutation, one launch
    PackJobs J;
    J.src[0] = x;       J.dst[0] = (float*)xc;    J.ngroups[0] = NTOK * HQ / 16;
    J.src[1] = gate_w1; J.dst[1] = (float*)wg1c;  J.ngroups[1] = G1Q * HQ / 16;
    J.src[2] = SVH1;    J.dst[2] = (float*)svh1c; J.ngroups[2] = EKQ * HQ / 16;
    J.src[3] = W1;      J.dst[3] = (float*)w1c;   J.ngroups[3] = FQ * HQ / 16;
    J.src[4] = SVH2;    J.dst[4] = (float*)svh2c; J.ngroups[4] = EKQ * FQ / 16;
    J.src[5] = W2;      J.dst[5] = (float*)w2c;   J.ngroups[5] = HQ * FQ / 16;
    k_pack6<<<dim3((NTOK * HQ / 16 + 255) / 256, 6), 256>>>(J);

    // 1: router, fused column-mean -> P8 [128][256]
    kr<<<dim3(G1Q / 128, NTOK / 64), 256, SM_RT>>>(
        xc, wg1c, HQ, nullptr, nullptr, 0, gate_b1, P8, nullptr, G1Q, 0);

    // 2: gw
    k_gwfin<<<BQ, 128>>>(P8, gate_w2, gate_b2, gwv);

    // 3: t1 partials = x @ SVH1^T, K split 2x384
    kt<<<dim3(1, NTOK / 64, 2), 256, SM_RT>>>(
        xc, svh1c, HQ, nullptr, nullptr, 0, nullptr, nullptr, t1p, EKQ, HQ / 2);

    // 4: t1s = fp16(sum_z t1p * gw), permuted
    k_red<2><<<NTOK * 64 / 256, 256>>>(t1p, gwv, t1s);

    // 5,6: transposed low-rank factors -> fp16 permuted
    k_tr_ilv<<<dim3(FQ / 32, 4), dim3(32, 8)>>>(U1, u1t, FQ);
    k_tr_ilv<<<dim3(HQ / 32, 4), dim3(32, 8)>>>(U2, u2t, HQ);

    // 7: merged biases (fp32)
    k_prep<<<(FQ + 255) / 256, 256>>>(b1, TB1, b2, TB2, b1m, b2m);

    // 8: h = fp16(relu(x @ W1^T + t1s @ U1 + b1m))   [8192,3072]
    k1<<<dim3(FQ / 128, NTOK / 128), 256, SM_F>>>(
        xc, w1c, HQ, t1s, u1t, EKQ, b1m, nullptr, hbuf, FQ, 0);

    // 9: t2 partials = h @ SVH2^T, K split 4x768
    kt<<<dim3(1, NTOK / 64, 4), 256, SM_RT>>>(
        hbuf, svh2c, FQ, nullptr, nullptr, 0, nullptr, nullptr, t2p, EKQ, FQ / 4);

    // 10: t2s = fp16(sum_z t2p * gw), permuted
    k_red<4><<<NTOK * 64 / 256, 256>>>(t2p, gwv, t2s);

    // 11: out = h @ W2^T + t2s @ U2 + b2m   [8192,768] fp32
    k2<<<dim3(HQ / 128, NTOK / 128), 256, SM_F>>>(
        hbuf, w2c, FQ, t2s, u2t, EKQ, b2m, nullptr, out, HQ, 0);
}

// round 13
// speedup vs baseline: 1.1708x; 1.0088x over previous
#include <cuda_runtime.h>
#include <cuda_fp16.h>
#include <cstdint>
#include <cstddef>

// ---------------------------------------------------------------------------
// RankOneMoE via fp16 mma.sync.m16n8k16 (fp32 accumulate). fp16 mantissa ==
// tf32 mantissa -> rn-rounded fp16 operands give tf32-grade accuracy.
//   gw[b,ek]  = (sum_s relu(x@gw1^T+b1g))[b,:]@gw2[ek,:]^T /512 + b2g[ek]
//   h         = relu([x | (x@SVH1^T)*gw] @ [W1^T ; U1] + b1m)
//   out       = [h | (h@SVH2^T)*gw] @ [W2^T ; U2] + b2m
// Per-16 k-pair permutation -> fragment = 1 LDS.64; rows padded to 96B.
// R13: fc restored to the TRUE R9-best shape (BM128xBN128, 4 warps of 64x64,
//      128 threads, 2 CTA/SM — R12 accidentally used the slower R8 shape);
//      router fused-mean kept (worth ~-4.5us); fc2 split-K x2 to kill its
//      1.3->2.0 wave quantization, with fused p0+p1+bias reduce.
// ---------------------------------------------------------------------------

#define BQ   16
#define SQ   512
#define HQ   768
#define FQ   3072
#define EQ   8
#define EKQ  128
#define G1Q  256
#define NTOK (BQ*SQ)      // 8192
#define LAMBDA 0.2f

// ---- scratch layout (float units; fp16 buffers use half the floats) ----
#define OFF_XC    0                         // 8192*768 h
#define OFF_WG1   3145728                   // 256*768 h
#define OFF_SVH1  3244032                   // 128*768 h
#define OFF_W1    3293184                   // 3072*768 h
#define OFF_U1T   4472832                   // 3072*128 h
#define OFF_SVH2  4669440                   // 128*3072 h
#define OFF_W2    4866048                   // 768*3072 h
#define OFF_U2T   6045696                   // 768*128 h
#define OFF_T1S   6094848                   // 8192*128 h
#define OFF_T2S   6619136                   // 8192*128 h
#define OFF_H     7143424                   // 8192*3072 h
#define OFF_T1P   19726336                  // 2*8192*128 f
#define OFF_T2P   21823488                  // 4*8192*128 f
#define OFF_OP    26017792                  // 2*8192*768 f (fc2 partials)
#define OFF_P8    38600704                  // 128*256 f
#define OFF_GWV   38633472                  // 16*128 f
#define OFF_B1M   38635520                  // 3072 f
#define OFF_B2M   38638592                  // 768 f
#define SCRATCH_FLOATS 38639872

static __device__ __align__(256) float g_scratch[SCRATCH_FLOATS];

// ---------------------------- helpers --------------------------------------
__device__ __forceinline__ uint32_t s2u(const void* p) {
    uint32_t a;
    asm("{ .reg .u64 t; cvta.to.shared.u64 t, %1; cvt.u32.u64 %0, t; }" : "=r"(a) : "l"(p));
    return a;
}
// position of original k (0..15) inside the permuted 16-group
__device__ __forceinline__ int ipos16(int k) {
    return (k & 1) + ((k >> 3) & 1) * 2 + (k & 6) * 2;
}
__device__ __forceinline__ void mma16(float* c,
                                      uint32_t a0, uint32_t a1, uint32_t a2, uint32_t a3,
                                      uint32_t b0, uint32_t b1) {
    asm volatile(
        "mma.sync.aligned.m16n8k16.row.col.f32.f16.f16.f32 "
        "{%0,%1,%2,%3},{%4,%5,%6,%7},{%8,%9},{%0,%1,%2,%3};\n"
        : "+f"(c[0]), "+f"(c[1]), "+f"(c[2]), "+f"(c[3])
        : "r"(a0), "r"(a1), "r"(a2), "r"(a3), "r"(b0), "r"(b1));
}

// ---------------------------- pack kernels ---------------------------------
struct PackJobs {
    const float* src[6];
    float*       dst[6];   // fp16 storage viewed as float words
    int          ngroups[6];
};

// fp32 -> fp16(rn) with per-16 k-pair permutation [0,1,8,9,2,3,10,11,...]
__global__ void k_pack6(PackJobs J) {
    const int job = blockIdx.y;
    const int g = blockIdx.x * blockDim.x + threadIdx.x;
    if (g >= J.ngroups[job]) return;
    const float4* s = reinterpret_cast<const float4*>(J.src[job]) + (size_t)g * 4;
    float4 v0 = s[0], v1 = s[1], v2 = s[2], v3 = s[3];
    __half2 h[8];
    h[0] = __floats2half2_rn(v0.x, v0.y);
    h[1] = __floats2half2_rn(v2.x, v2.y);
    h[2] = __floats2half2_rn(v0.z, v0.w);
    h[3] = __floats2half2_rn(v2.z, v2.w);
    h[4] = __floats2half2_rn(v1.x, v1.y);
    h[5] = __floats2half2_rn(v3.x, v3.y);
    h[6] = __floats2half2_rn(v1.z, v1.w);
    h[7] = __floats2half2_rn(v3.z, v3.w);
    float4* d = reinterpret_cast<float4*>(reinterpret_cast<__half*>(J.dst[job]) + (size_t)g * 16);
    d[0] = *reinterpret_cast<float4*>(&h[0]);
    d[1] = *reinterpret_cast<float4*>(&h[4]);
}

// transpose src[128, Ncols] f32 -> dst[Ncols, 128] fp16 permuted
__global__ void k_tr_ilv(const float* __restrict__ S_, __half* __restrict__ Dst, int Ncols) {
    __shared__ float t[32][33];
    const int nx = blockIdx.x * 32, my = blockIdx.y * 32;
    const int x = threadIdx.x, y = threadIdx.y;
    #pragma unroll
    for (int i = 0; i < 32; i += 8)
        t[y + i][x] = S_[(size_t)(my + y + i) * Ncols + nx + x];
    __syncthreads();
    #pragma unroll
    for (int i = 0; i < 32; i += 8) {
        const int r = my + x;
        const int pos = (r & ~15) + ipos16(r & 15);
        Dst[(size_t)(nx + y + i) * 128 + pos] = __float2half_rn(t[x][y + i]);
    }
}

__global__ void k_prep(const float* __restrict__ b1, const float* __restrict__ tb1,
                       const float* __restrict__ b2, const float* __restrict__ tb2,
                       float* __restrict__ b1m, float* __restrict__ b2m) {
    int i = blockIdx.x * blockDim.x + threadIdx.x;
    if (i < FQ) {
        float s = 0.f;
        #pragma unroll
        for (int e = 0; e < EQ; ++e) s += tb1[e * FQ + i];
        b1m[i] = b1[i] + LAMBDA * s;
    }
    if (i < HQ) {
        float s = 0.f;
        #pragma unroll
        for (int e = 0; e < EQ; ++e) s += tb2[e * HQ + i];
        b2m[i] = b2[i] + LAMBDA * s;
    }
}

// gw[b,ek] = dot(P[b,:], w2[ek,:]) / 512 + gb2[ek]   (P8: [128 chunks][256])
__global__ void k_gwfin(const float* __restrict__ P8, const float* __restrict__ w2,
                        const float* __restrict__ gb2, float* __restrict__ gw) {
    __shared__ float Ps[G1Q];
    int b = blockIdx.x, t = threadIdx.x;   // 128 threads
    #pragma unroll
    for (int half = 0; half < 2; ++half) {
        int col = t + half * 128;
        float a = 0.f;
        #pragma unroll
        for (int ch = 0; ch < 8; ++ch) a += P8[(b * 8 + ch) * G1Q + col];
        Ps[col] = a;
    }
    __syncthreads();
    const float* w = w2 + (size_t)t * G1Q;
    float a = 0.f;
    #pragma unroll 8
    for (int g = 0; g < G1Q; ++g) a += w[g] * Ps[g];
    gw[b * EKQ + t] = a * (1.0f / (float)SQ) + gb2[t];
}

// split-K reduce: sum KS partials, scale by gw, convert to fp16 permuted
template<int KS>
__global__ void k_red(const float* __restrict__ tp, const float* __restrict__ gwv,
                      __half* __restrict__ ts) {
    const int idx = blockIdx.x * 256 + threadIdx.x;   // over NTOK*64 pairs
    const int r = idx >> 6, c = (idx & 63) * 2;
    float v0 = tp[(size_t)r * EKQ + c];
    float v1 = tp[(size_t)r * EKQ + c + 1];
    #pragma unroll
    for (int z = 1; z < KS; ++z) {
        v0 += tp[(size_t)z * NTOK * EKQ + (size_t)r * EKQ + c];
        v1 += tp[(size_t)z * NTOK * EKQ + (size_t)r * EKQ + c + 1];
    }
    const int gb = (r >> 9) << 7;
    v0 *= gwv[gb + c]; v1 *= gwv[gb + c + 1];
    const int pos = (c & ~15) + ipos16(c & 15);
    *reinterpret_cast<__half2*>(ts + (size_t)r * EKQ + pos) = __floats2half2_rn(v0, v1);
}

// fc2 final: out = p0 + p1 + b2m   (fp32, [8192, 768])
__global__ void k_redout(const float* __restrict__ op, const float* __restrict__ b2m,
                         float* __restrict__ out) {
    const int i = blockIdx.x * 256 + threadIdx.x;      // float4 index
    const float4 p0 = reinterpret_cast<const float4*>(op)[i];
    const float4 p1 = reinterpret_cast<const float4*>(op + (size_t)NTOK * HQ)[i];
    const int c = (i * 4) % HQ;
    float4 o;
    o.x = p0.x + p1.x + b2m[c];
    o.y = p0.y + p1.y + b2m[c + 1];
    o.z = p0.z + p1.z + b2m[c + 2];
    o.w = p0.w + p1.w + b2m[c + 3];
    reinterpret_cast<float4*>(out)[i] = o;
}

// ---------------------------------------------------------------------------
// Pipelined fp16 mma.sync GEMM. BK=32 per stage, STAGES-deep cp.async.
//   D = epi( A1[M,K1] @ B1[N,K1]^T (+ A2[M,K2] @ B2[N,K2]^T) )
//   EPI: 0=none, 1=relu, 3=router (relu + column-sum over BM rows -> aux).
//   OUTH: fp16 permuted output. SPLITK: z picks kspan window of K1; A2 tail
//   (if HAS2) runs only in the last z; D offset by z*NTOK*N.
// ---------------------------------------------------------------------------
template<int BM, int BN, int WM, int WN, int STAGES, int EPI,
         bool HAS2, bool HAS_BIAS, bool OUTH, bool SPLITK, int OCC>
__global__ void __launch_bounds__(WM * WN * 32, OCC)
k_mma(const __half* __restrict__ A1, const __half* __restrict__ B1, int K1,
      const __half* __restrict__ A2, const __half* __restrict__ B2, int K2,
      const float* __restrict__ bias, float* __restrict__ aux,
      void* __restrict__ Dv, int N, int kspan)
{
    constexpr int THREADS = WM * WN * 32;
    constexpr int WTM = BM / WM, WTN = BN / WN;
    constexpr int MT = WTM / 16, NT = WTN / 8;
    constexpr int RB = 96;                        // padded row bytes (64B data)
    constexpr int STGB = (BM + BN) * RB;
    constexpr int AIT = (BM * 4) / THREADS;
    constexpr int BIT = (BN * 4) / THREADS;

    extern __shared__ char sm[];
    const uint32_t smb = s2u(sm);

    const int tid = threadIdx.x;
    const int wid = tid >> 5, lane = tid & 31;
    const int gid = lane >> 2, tig = lane & 3;
    const int wm = (wid / WN) * WTM;
    const int wn = (wid % WN) * WTN;
    const int bM = blockIdx.y * BM;
    const int bN = blockIdx.x * BN;
    const int kbase = SPLITK ? blockIdx.z * kspan : 0;
    const int T1S = SPLITK ? (kspan >> 5) : (K1 >> 5);
    const bool tail = HAS2 && (!SPLITK || blockIdx.z == gridDim.z - 1);
    const int TS = T1S + (tail ? (K2 >> 5) : 0);

    float acc[MT][NT][4];
    #pragma unroll
    for (int mi = 0; mi < MT; ++mi)
        #pragma unroll
        for (int ni = 0; ni < NT; ++ni)
            #pragma unroll
            for (int j = 0; j < 4; ++j) acc[mi][ni][j] = 0.f;

    auto issue = [&](int jj) {
        const __half* a; const __half* b; int lda, ldb, k0;
        if (!HAS2 || jj < T1S) { a = A1; lda = K1; b = B1; ldb = K1; k0 = kbase + (jj << 5); }
        else                   { a = A2; lda = K2; b = B2; ldb = K2; k0 = (jj - T1S) << 5; }
        const uint32_t sA = smb + (uint32_t)((jj % STAGES) * STGB);
        const uint32_t sB = sA + (uint32_t)BM * RB;
        #pragma unroll
        for (int i = 0; i < AIT; ++i) {
            int idx = tid + i * THREADS; int r = idx >> 2, c = idx & 3;
            const __half* src = a + (size_t)(bM + r) * lda + k0 + c * 8;
            asm volatile("cp.async.cg.shared.global [%0], [%1], 16;\n"
                         :: "r"(sA + (uint32_t)(r * RB + c * 16)), "l"(src) : "memory");
        }
        #pragma unroll
        for (int i = 0; i < BIT; ++i) {
            int idx = tid + i * THREADS; int r = idx >> 2, c = idx & 3;
            const __half* src = b + (size_t)(bN + r) * ldb + k0 + c * 8;
            asm volatile("cp.async.cg.shared.global [%0], [%1], 16;\n"
                         :: "r"(sB + (uint32_t)(r * RB + c * 16)), "l"(src) : "memory");
        }
    };

    #pragma unroll
    for (int s = 0; s < STAGES - 1; ++s) {
        issue(s);
        asm volatile("cp.async.commit_group;\n" ::: "memory");
    }

    for (int j = 0; j < TS; ++j) {
        asm volatile("cp.async.wait_group %0;\n" :: "n"(STAGES - 2) : "memory");
        __syncthreads();

        const char* sst = sm + (j % STAGES) * STGB;
        const char* sA = sst;
        const char* sB = sst + BM * RB;

        #pragma unroll
        for (int g = 0; g < 2; ++g) {
            uint2 fb[NT];
            #pragma unroll
            for (int ni = 0; ni < NT; ++ni)
                fb[ni] = *reinterpret_cast<const uint2*>(
                    sB + (wn + ni * 8 + gid) * RB + g * 32 + tig * 8);

            if (g == 0) {
                if (j + STAGES - 1 < TS) issue(j + STAGES - 1);
                asm volatile("cp.async.commit_group;\n" ::: "memory");
            }

            #pragma unroll
            for (int mi = 0; mi < MT; ++mi) {
                const char* ra = sA + (wm + mi * 16 + gid) * RB + g * 32 + tig * 8;
                const uint2 fa0 = *reinterpret_cast<const uint2*>(ra);
                const uint2 fa1 = *reinterpret_cast<const uint2*>(ra + 8 * RB);
                #pragma unroll
                for (int ni = 0; ni < NT; ++ni)
                    mma16(acc[mi][ni], fa0.x, fa1.x, fa0.y, fa1.y,
                          fb[ni].x, fb[ni].y);
            }
        }
    }

    if (EPI == 3) {
        // router: aux[blockIdx.y][bN + col] = sum_rows relu(acc + bias)
        float part[NT][2];
        #pragma unroll
        for (int ni = 0; ni < NT; ++ni) { part[ni][0] = 0.f; part[ni][1] = 0.f; }
        #pragma unroll
        for (int ni = 0; ni < NT; ++ni) {
            const int cl = wn + ni * 8 + tig * 2;
            const float bb0 = bias[bN + cl], bb1 = bias[bN + cl + 1];
            #pragma unroll
            for (int mi = 0; mi < MT; ++mi)
                #pragma unroll
                for (int h = 0; h < 2; ++h) {
                    part[ni][0] += fmaxf(acc[mi][ni][2 * h + 0] + bb0, 0.f);
                    part[ni][1] += fmaxf(acc[mi][ni][2 * h + 1] + bb1, 0.f);
                }
        }
        #pragma unroll
        for (int ni = 0; ni < NT; ++ni)
            #pragma unroll
            for (int j2 = 0; j2 < 2; ++j2) {
                float v = part[ni][j2];
                v += __shfl_xor_sync(0xffffffffu, v, 4);
                v += __shfl_xor_sync(0xffffffffu, v, 8);
                v += __shfl_xor_sync(0xffffffffu, v, 16);
                part[ni][j2] = v;                        // valid in lanes 0-3
            }
        asm volatile("cp.async.wait_group 0;\n" ::: "memory");
        __syncthreads();
        float* red = reinterpret_cast<float*>(sm);       // reuse stage smem
        if (tid < BN) red[tid] = 0.f;
        __syncthreads();
        const int wrow = wid / WN;                       // WM == 2 assumed
        if (wrow == 0 && lane < 4) {
            #pragma unroll
            for (int ni = 0; ni < NT; ++ni) {
                red[wn + ni * 8 + lane * 2]     = part[ni][0];
                red[wn + ni * 8 + lane * 2 + 1] = part[ni][1];
            }
        }
        __syncthreads();
        if (wrow == 1 && lane < 4) {
            #pragma unroll
            for (int ni = 0; ni < NT; ++ni) {
                red[wn + ni * 8 + lane * 2]     += part[ni][0];
                red[wn + ni * 8 + lane * 2 + 1] += part[ni][1];
            }
        }
        __syncthreads();
        if (tid < BN)
            aux[(size_t)blockIdx.y * G1Q + bN + tid] = red[tid];
        return;
    }

    // normal epilogue
    float* Df = reinterpret_cast<float*>(Dv)
              + (SPLITK ? (size_t)blockIdx.z * NTOK * N : 0);
    __half* Dh = reinterpret_cast<__half*>(Dv);
    #pragma unroll
    for (int mi = 0; mi < MT; ++mi) {
        const int r0 = bM + wm + mi * 16 + gid;
        #pragma unroll
        for (int ni = 0; ni < NT; ++ni) {
            const int cl = wn + ni * 8 + tig * 2;
            const int c  = bN + cl;
            const float bb0 = HAS_BIAS ? bias[c] : 0.f;
            const float bb1 = HAS_BIAS ? bias[c + 1] : 0.f;
            #pragma unroll
            for (int h = 0; h < 2; ++h) {
                const int r = r0 + h * 8;
                float v0 = acc[mi][ni][2 * h + 0] + bb0;
                float v1 = acc[mi][ni][2 * h + 1] + bb1;
                if (EPI == 1) { v0 = fmaxf(v0, 0.f); v1 = fmaxf(v1, 0.f); }
                if (OUTH) {
                    const int pos = (c & ~15) + ipos16(c & 15);
                    *reinterpret_cast<__half2*>(Dh + (size_t)r * N + pos) =
                        __floats2half2_rn(v0, v1);
                } else {
                    *reinterpret_cast<float2*>(Df + (size_t)r * N + c) = make_float2(v0, v1);
                }
            }
        }
    }
}

// ---------------------------------------------------------------------------
extern "C" void kernel_launch(void* const* d_in, const int* in_sizes, int n_in,
                              void* d_out, int out_size) {
    const float* x       = (const float*)d_in[0];
    const float* gate_w1 = (const float*)d_in[1];
    const float* gate_b1 = (const float*)d_in[2];
    const float* gate_w2 = (const float*)d_in[3];
    const float* gate_b2 = (const float*)d_in[4];
    const float* W1      = (const float*)d_in[5];
    const float* b1      = (const float*)d_in[6];
    const float* W2      = (const float*)d_in[7];
    const float* b2      = (const float*)d_in[8];
    const float* U1      = (const float*)d_in[9];
    const float* SVH1    = (const float*)d_in[10];
    const float* U2      = (const float*)d_in[11];
    const float* SVH2    = (const float*)d_in[12];
    const float* TB1     = (const float*)d_in[13];
    const float* TB2     = (const float*)d_in[14];
    float* out = (float*)d_out;

    float* S = nullptr;
    cudaGetSymbolAddress((void**)&S, g_scratch);
    __half* xc    = (__half*)(S + OFF_XC);
    __half* wg1c  = (__half*)(S + OFF_WG1);
    __half* svh1c = (__half*)(S + OFF_SVH1);
    __half* w1c   = (__half*)(S + OFF_W1);
    __half* u1t   = (__half*)(S + OFF_U1T);
    __half* svh2c = (__half*)(S + OFF_SVH2);
    __half* w2c   = (__half*)(S + OFF_W2);
    __half* u2t   = (__half*)(S + OFF_U2T);
    __half* t1s   = (__half*)(S + OFF_T1S);
    __half* t2s   = (__half*)(S + OFF_T2S);
    __half* hbuf  = (__half*)(S + OFF_H);
    float* t1p   = S + OFF_T1P;
    float* t2p   = S + OFF_T2P;
    float* op    = S + OFF_OP;
    float* P8    = S + OFF_P8;
    float* gwv   = S + OFF_GWV;
    float* b1m   = S + OFF_B1M;
    float* b2m   = S + OFF_B2M;

    // router: BM64 BN128, 8 warps (2x4) 32x32, 4 stages, fused mean -> P8
    auto kr = k_mma<64, 128, 2, 4, 4, 3, false, true, false, false, 2>;
    // t partial GEMMs: BM64 BN128, split-K, fp32 raw partials
    auto kt = k_mma<64, 128, 2, 4, 4, 0, false, false, false, true, 2>;
    // fc1: BM128 BN128, 4 warps (2x2) of 64x64, 128 thr, 2 CTA/SM (true R9)
    auto k1 = k_mma<128, 128, 2, 2, 4, 1, true, true, true, false, 2>;
    // fc2: same shape, split-K x2 (z1 carries the U2 tail), fp32 partials
    auto k2 = k_mma<128, 128, 2, 2, 4, 0, true, false, false, true, 2>;

    const int SM_RT = 4 * (64 + 128) * 96;      // 73728
    const int SM_F  = 4 * (128 + 128) * 96;     // 98304
    cudaFuncSetAttribute((const void*)kr, cudaFuncAttributeMaxDynamicSharedMemorySize, SM_RT);
    cudaFuncSetAttribute((const void*)kt, cudaFuncAttributeMaxDynamicSharedMemorySize, SM_RT);
    cudaFuncSetAttribute((const void*)k1, cudaFuncAttributeMaxDynamicSharedMemorySize, SM_F);
    cudaFuncSetAttribute((const void*)k2, cudaFuncAttributeMaxDynamicSharedMemorySize, SM_F);

    // 0: all fp32->fp16(rn) packs with k-permutation, one launch
    PackJobs J;
    J.src[0] = x;       J.dst[0] = (float*)xc;    J.ngroups[0] = NTOK * HQ / 16;
    J.src[1] = gate_w1; J.dst[1] = (float*)wg1c;  J.ngroups[1] = G1Q * HQ / 16;
    J.src[2] = SVH1;    J.dst[2] = (float*)svh1c; J.ngroups[2] = EKQ * HQ / 16;
    J.src[3] = W1;      J.dst[3] = (float*)w1c;   J.ngroups[3] = FQ * HQ / 16;
    J.src[4] = SVH2;    J.dst[4] = (float*)svh2c; J.ngroups[4] = EKQ * FQ / 16;
    J.src[5] = W2;      J.dst[5] = (float*)w2c;   J.ngroups[5] = HQ * FQ / 16;
    k_pack6<<<dim3((NTOK * HQ / 16 + 255) / 256, 6), 256>>>(J);

    // 1: router, fused column-mean -> P8 [128][256]
    kr<<<dim3(G1Q / 128, NTOK / 64), 256, SM_RT>>>(
        xc, wg1c, HQ, nullptr, nullptr, 0, gate_b1, P8, nullptr, G1Q, 0);

    // 2: gw
    k_gwfin<<<BQ, 128>>>(P8, gate_w2, gate_b2, gwv);

    // 3: t1 partials = x @ SVH1^T, K split 2x384
    kt<<<dim3(1, NTOK / 64, 2), 256, SM_RT>>>(
        xc, svh1c, HQ, nullptr, nullptr, 0, nullptr, nullptr, t1p, EKQ, HQ / 2);

    // 4: t1s = fp16(sum_z t1p * gw), permuted
    k_red<2><<<NTOK * 64 / 256, 256>>>(t1p, gwv, t1s);

    // 5,6: transposed low-rank factors -> fp16 permuted
    k_tr_ilv<<<dim3(FQ / 32, 4), dim3(32, 8)>>>(U1, u1t, FQ);
    k_tr_ilv<<<dim3(HQ / 32, 4), dim3(32, 8)>>>(U2, u2t, HQ);

    // 7: merged biases (fp32)
    k_prep<<<(FQ + 255) / 256, 256>>>(b1, TB1, b2, TB2, b1m, b2m);

    // 8: h = fp16(relu(x @ W1^T + t1s @ U1 + b1m))   [8192,3072]
    k1<<<dim3(FQ / 128, NTOK / 128), 128, SM_F>>>(
        xc, w1c, HQ, t1s, u1t, EKQ, b1m, nullptr, hbuf, FQ, 0);

    // 9: t2 partials = h @ SVH2^T, K split 4x768
    kt<<<dim3(1, NTOK / 64, 4), 256, SM_RT>>>(
        hbuf, svh2c, FQ, nullptr, nullptr, 0, nullptr, nullptr, t2p, EKQ, FQ / 4);

    // 10: t2s = fp16(sum_z t2p * gw), permuted
    k_red<4><<<NTOK * 64 / 256, 256>>>(t2p, gwv, t2s);

    // 11: fc2 partials: z0 = h@W2^T[k 0:1536], z1 = h@W2^T[k 1536:3072] + t2s@U2
    k2<<<dim3(HQ / 128, NTOK / 128, 2), 128, SM_F>>>(
        hbuf, w2c, FQ, t2s, u2t, EKQ, nullptr, nullptr, op, HQ, FQ / 2);

    // 12: out = p0 + p1 + b2m
    k_redout<<<NTOK * HQ / 4 / 256, 256>>>(op, b2m, out);
}

// round 14
// speedup vs baseline: 1.2062x; 1.0303x over previous
#include <cuda_runtime.h>
#include <cuda_fp16.h>
#include <cstdint>
#include <cstddef>

// ---------------------------------------------------------------------------
// RankOneMoE via fp16 mma.sync.m16n8k16 (fp32 accumulate). fp16 mantissa ==
// tf32 mantissa -> rn-rounded fp16 operands give tf32-grade accuracy.
//   gw[b,ek]  = (sum_s relu(x@gw1^T+b1g))[b,:]@gw2[ek,:]^T /512 + b2g[ek]
//   h         = relu([x | (x@SVH1^T)*gw] @ [W1^T ; U1] + b1m)
//   out       = [h | (h@SVH2^T)*gw] @ [W2^T ; U2] + b2m
// Per-16 k-pair permutation -> fragment = 1 LDS.64; rows padded to 96B.
// R14: consolidation of measured-best components. fc1 AND fc2 in the exact
//      R9 shape (BM128xBN128, 4 warps of 64x64, 128 thr, 2 CTA/SM, direct
//      epilogues — fc2 split-K measured +10us twice, reverted). Router
//      fused column-mean kept (measured -4.5us).
// ---------------------------------------------------------------------------

#define BQ   16
#define SQ   512
#define HQ   768
#define FQ   3072
#define EQ   8
#define EKQ  128
#define G1Q  256
#define NTOK (BQ*SQ)      // 8192
#define LAMBDA 0.2f

// ---- scratch layout (float units; fp16 buffers use half the floats) ----
#define OFF_XC    0                         // 8192*768 h
#define OFF_WG1   3145728                   // 256*768 h
#define OFF_SVH1  3244032                   // 128*768 h
#define OFF_W1    3293184                   // 3072*768 h
#define OFF_U1T   4472832                   // 3072*128 h
#define OFF_SVH2  4669440                   // 128*3072 h
#define OFF_W2    4866048                   // 768*3072 h
#define OFF_U2T   6045696                   // 768*128 h
#define OFF_T1S   6094848                   // 8192*128 h
#define OFF_T2S   6619136                   // 8192*128 h
#define OFF_H     7143424                   // 8192*3072 h
#define OFF_T1P   19726336                  // 2*8192*128 f
#define OFF_T2P   21823488                  // 4*8192*128 f
#define OFF_P8    26017792                  // 128*256 f
#define OFF_GWV   26050560                  // 16*128 f
#define OFF_B1M   26052608                  // 3072 f
#define OFF_B2M   26055680                  // 768 f
#define SCRATCH_FLOATS 26056448

static __device__ __align__(256) float g_scratch[SCRATCH_FLOATS];

// ---------------------------- helpers --------------------------------------
__device__ __forceinline__ uint32_t s2u(const void* p) {
    uint32_t a;
    asm("{ .reg .u64 t; cvta.to.shared.u64 t, %1; cvt.u32.u64 %0, t; }" : "=r"(a) : "l"(p));
    return a;
}
// position of original k (0..15) inside the permuted 16-group
__device__ __forceinline__ int ipos16(int k) {
    return (k & 1) + ((k >> 3) & 1) * 2 + (k & 6) * 2;
}
__device__ __forceinline__ void mma16(float* c,
                                      uint32_t a0, uint32_t a1, uint32_t a2, uint32_t a3,
                                      uint32_t b0, uint32_t b1) {
    asm volatile(
        "mma.sync.aligned.m16n8k16.row.col.f32.f16.f16.f32 "
        "{%0,%1,%2,%3},{%4,%5,%6,%7},{%8,%9},{%0,%1,%2,%3};\n"
        : "+f"(c[0]), "+f"(c[1]), "+f"(c[2]), "+f"(c[3])
        : "r"(a0), "r"(a1), "r"(a2), "r"(a3), "r"(b0), "r"(b1));
}

// ---------------------------- pack kernels ---------------------------------
struct PackJobs {
    const float* src[6];
    float*       dst[6];   // fp16 storage viewed as float words
    int          ngroups[6];
};

// fp32 -> fp16(rn) with per-16 k-pair permutation [0,1,8,9,2,3,10,11,...]
__global__ void k_pack6(PackJobs J) {
    const int job = blockIdx.y;
    const int g = blockIdx.x * blockDim.x + threadIdx.x;
    if (g >= J.ngroups[job]) return;
    const float4* s = reinterpret_cast<const float4*>(J.src[job]) + (size_t)g * 4;
    float4 v0 = s[0], v1 = s[1], v2 = s[2], v3 = s[3];
    __half2 h[8];
    h[0] = __floats2half2_rn(v0.x, v0.y);
    h[1] = __floats2half2_rn(v2.x, v2.y);
    h[2] = __floats2half2_rn(v0.z, v0.w);
    h[3] = __floats2half2_rn(v2.z, v2.w);
    h[4] = __floats2half2_rn(v1.x, v1.y);
    h[5] = __floats2half2_rn(v3.x, v3.y);
    h[6] = __floats2half2_rn(v1.z, v1.w);
    h[7] = __floats2half2_rn(v3.z, v3.w);
    float4* d = reinterpret_cast<float4*>(reinterpret_cast<__half*>(J.dst[job]) + (size_t)g * 16);
    d[0] = *reinterpret_cast<float4*>(&h[0]);
    d[1] = *reinterpret_cast<float4*>(&h[4]);
}

// transpose src[128, Ncols] f32 -> dst[Ncols, 128] fp16 permuted
__global__ void k_tr_ilv(const float* __restrict__ S_, __half* __restrict__ Dst, int Ncols) {
    __shared__ float t[32][33];
    const int nx = blockIdx.x * 32, my = blockIdx.y * 32;
    const int x = threadIdx.x, y = threadIdx.y;
    #pragma unroll
    for (int i = 0; i < 32; i += 8)
        t[y + i][x] = S_[(size_t)(my + y + i) * Ncols + nx + x];
    __syncthreads();
    #pragma unroll
    for (int i = 0; i < 32; i += 8) {
        const int r = my + x;
        const int pos = (r & ~15) + ipos16(r & 15);
        Dst[(size_t)(nx + y + i) * 128 + pos] = __float2half_rn(t[x][y + i]);
    }
}

__global__ void k_prep(const float* __restrict__ b1, const float* __restrict__ tb1,
                       const float* __restrict__ b2, const float* __restrict__ tb2,
                       float* __restrict__ b1m, float* __restrict__ b2m) {
    int i = blockIdx.x * blockDim.x + threadIdx.x;
    if (i < FQ) {
        float s = 0.f;
        #pragma unroll
        for (int e = 0; e < EQ; ++e) s += tb1[e * FQ + i];
        b1m[i] = b1[i] + LAMBDA * s;
    }
    if (i < HQ) {
        float s = 0.f;
        #pragma unroll
        for (int e = 0; e < EQ; ++e) s += tb2[e * HQ + i];
        b2m[i] = b2[i] + LAMBDA * s;
    }
}

// gw[b,ek] = dot(P[b,:], w2[ek,:]) / 512 + gb2[ek]   (P8: [128 chunks][256])
__global__ void k_gwfin(const float* __restrict__ P8, const float* __restrict__ w2,
                        const float* __restrict__ gb2, float* __restrict__ gw) {
    __shared__ float Ps[G1Q];
    int b = blockIdx.x, t = threadIdx.x;   // 128 threads
    #pragma unroll
    for (int half = 0; half < 2; ++half) {
        int col = t + half * 128;
        float a = 0.f;
        #pragma unroll
        for (int ch = 0; ch < 8; ++ch) a += P8[(b * 8 + ch) * G1Q + col];
        Ps[col] = a;
    }
    __syncthreads();
    const float* w = w2 + (size_t)t * G1Q;
    float a = 0.f;
    #pragma unroll 8
    for (int g = 0; g < G1Q; ++g) a += w[g] * Ps[g];
    gw[b * EKQ + t] = a * (1.0f / (float)SQ) + gb2[t];
}

// split-K reduce: sum KS partials, scale by gw, convert to fp16 permuted
template<int KS>
__global__ void k_red(const float* __restrict__ tp, const float* __restrict__ gwv,
                      __half* __restrict__ ts) {
    const int idx = blockIdx.x * 256 + threadIdx.x;   // over NTOK*64 pairs
    const int r = idx >> 6, c = (idx & 63) * 2;
    float v0 = tp[(size_t)r * EKQ + c];
    float v1 = tp[(size_t)r * EKQ + c + 1];
    #pragma unroll
    for (int z = 1; z < KS; ++z) {
        v0 += tp[(size_t)z * NTOK * EKQ + (size_t)r * EKQ + c];
        v1 += tp[(size_t)z * NTOK * EKQ + (size_t)r * EKQ + c + 1];
    }
    const int gb = (r >> 9) << 7;
    v0 *= gwv[gb + c]; v1 *= gwv[gb + c + 1];
    const int pos = (c & ~15) + ipos16(c & 15);
    *reinterpret_cast<__half2*>(ts + (size_t)r * EKQ + pos) = __floats2half2_rn(v0, v1);
}

// ---------------------------------------------------------------------------
// Pipelined fp16 mma.sync GEMM. BK=32 per stage, STAGES-deep cp.async.
//   D = epi( A1[M,K1] @ B1[N,K1]^T (+ A2[M,K2] @ B2[N,K2]^T) )
//   EPI: 0=none, 1=relu, 3=router (relu + column-sum over BM rows -> aux).
//   OUTH: fp16 permuted output. SPLITK: z picks kspan window of K1; A2 tail
//   (if HAS2) runs only in the last z; D offset by z*NTOK*N.
// ---------------------------------------------------------------------------
template<int BM, int BN, int WM, int WN, int STAGES, int EPI,
         bool HAS2, bool HAS_BIAS, bool OUTH, bool SPLITK, int OCC>
__global__ void __launch_bounds__(WM * WN * 32, OCC)
k_mma(const __half* __restrict__ A1, const __half* __restrict__ B1, int K1,
      const __half* __restrict__ A2, const __half* __restrict__ B2, int K2,
      const float* __restrict__ bias, float* __restrict__ aux,
      void* __restrict__ Dv, int N, int kspan)
{
    constexpr int THREADS = WM * WN * 32;
    constexpr int WTM = BM / WM, WTN = BN / WN;
    constexpr int MT = WTM / 16, NT = WTN / 8;
    constexpr int RB = 96;                        // padded row bytes (64B data)
    constexpr int STGB = (BM + BN) * RB;
    constexpr int AIT = (BM * 4) / THREADS;
    constexpr int BIT = (BN * 4) / THREADS;

    extern __shared__ char sm[];
    const uint32_t smb = s2u(sm);

    const int tid = threadIdx.x;
    const int wid = tid >> 5, lane = tid & 31;
    const int gid = lane >> 2, tig = lane & 3;
    const int wm = (wid / WN) * WTM;
    const int wn = (wid % WN) * WTN;
    const int bM = blockIdx.y * BM;
    const int bN = blockIdx.x * BN;
    const int kbase = SPLITK ? blockIdx.z * kspan : 0;
    const int T1S = SPLITK ? (kspan >> 5) : (K1 >> 5);
    const bool tail = HAS2 && (!SPLITK || blockIdx.z == gridDim.z - 1);
    const int TS = T1S + (tail ? (K2 >> 5) : 0);

    float acc[MT][NT][4];
    #pragma unroll
    for (int mi = 0; mi < MT; ++mi)
        #pragma unroll
        for (int ni = 0; ni < NT; ++ni)
            #pragma unroll
            for (int j = 0; j < 4; ++j) acc[mi][ni][j] = 0.f;

    auto issue = [&](int jj) {
        const __half* a; const __half* b; int lda, ldb, k0;
        if (!HAS2 || jj < T1S) { a = A1; lda = K1; b = B1; ldb = K1; k0 = kbase + (jj << 5); }
        else                   { a = A2; lda = K2; b = B2; ldb = K2; k0 = (jj - T1S) << 5; }
        const uint32_t sA = smb + (uint32_t)((jj % STAGES) * STGB);
        const uint32_t sB = sA + (uint32_t)BM * RB;
        #pragma unroll
        for (int i = 0; i < AIT; ++i) {
            int idx = tid + i * THREADS; int r = idx >> 2, c = idx & 3;
            const __half* src = a + (size_t)(bM + r) * lda + k0 + c * 8;
            asm volatile("cp.async.cg.shared.global [%0], [%1], 16;\n"
                         :: "r"(sA + (uint32_t)(r * RB + c * 16)), "l"(src) : "memory");
        }
        #pragma unroll
        for (int i = 0; i < BIT; ++i) {
            int idx = tid + i * THREADS; int r = idx >> 2, c = idx & 3;
            const __half* src = b + (size_t)(bN + r) * ldb + k0 + c * 8;
            asm volatile("cp.async.cg.shared.global [%0], [%1], 16;\n"
                         :: "r"(sB + (uint32_t)(r * RB + c * 16)), "l"(src) : "memory");
        }
    };

    #pragma unroll
    for (int s = 0; s < STAGES - 1; ++s) {
        issue(s);
        asm volatile("cp.async.commit_group;\n" ::: "memory");
    }

    for (int j = 0; j < TS; ++j) {
        asm volatile("cp.async.wait_group %0;\n" :: "n"(STAGES - 2) : "memory");
        __syncthreads();

        const char* sst = sm + (j % STAGES) * STGB;
        const char* sA = sst;
        const char* sB = sst + BM * RB;

        #pragma unroll
        for (int g = 0; g < 2; ++g) {
            uint2 fb[NT];
            #pragma unroll
            for (int ni = 0; ni < NT; ++ni)
                fb[ni] = *reinterpret_cast<const uint2*>(
                    sB + (wn + ni * 8 + gid) * RB + g * 32 + tig * 8);

            if (g == 0) {
                if (j + STAGES - 1 < TS) issue(j + STAGES - 1);
                asm volatile("cp.async.commit_group;\n" ::: "memory");
            }

            #pragma unroll
            for (int mi = 0; mi < MT; ++mi) {
                const char* ra = sA + (wm + mi * 16 + gid) * RB + g * 32 + tig * 8;
                const uint2 fa0 = *reinterpret_cast<const uint2*>(ra);
                const uint2 fa1 = *reinterpret_cast<const uint2*>(ra + 8 * RB);
                #pragma unroll
                for (int ni = 0; ni < NT; ++ni)
                    mma16(acc[mi][ni], fa0.x, fa1.x, fa0.y, fa1.y,
                          fb[ni].x, fb[ni].y);
            }
        }
    }

    if (EPI == 3) {
        // router: aux[blockIdx.y][bN + col] = sum_rows relu(acc + bias)
        float part[NT][2];
        #pragma unroll
        for (int ni = 0; ni < NT; ++ni) { part[ni][0] = 0.f; part[ni][1] = 0.f; }
        #pragma unroll
        for (int ni = 0; ni < NT; ++ni) {
            const int cl = wn + ni * 8 + tig * 2;
            const float bb0 = bias[bN + cl], bb1 = bias[bN + cl + 1];
            #pragma unroll
            for (int mi = 0; mi < MT; ++mi)
                #pragma unroll
                for (int h = 0; h < 2; ++h) {
                    part[ni][0] += fmaxf(acc[mi][ni][2 * h + 0] + bb0, 0.f);
                    part[ni][1] += fmaxf(acc[mi][ni][2 * h + 1] + bb1, 0.f);
                }
        }
        #pragma unroll
        for (int ni = 0; ni < NT; ++ni)
            #pragma unroll
            for (int j2 = 0; j2 < 2; ++j2) {
                float v = part[ni][j2];
                v += __shfl_xor_sync(0xffffffffu, v, 4);
                v += __shfl_xor_sync(0xffffffffu, v, 8);
                v += __shfl_xor_sync(0xffffffffu, v, 16);
                part[ni][j2] = v;                        // valid in lanes 0-3
            }
        asm volatile("cp.async.wait_group 0;\n" ::: "memory");
        __syncthreads();
        float* red = reinterpret_cast<float*>(sm);       // reuse stage smem
        if (tid < BN) red[tid] = 0.f;
        __syncthreads();
        const int wrow = wid / WN;                       // WM == 2 assumed
        if (wrow == 0 && lane < 4) {
            #pragma unroll
            for (int ni = 0; ni < NT; ++ni) {
                red[wn + ni * 8 + lane * 2]     = part[ni][0];
                red[wn + ni * 8 + lane * 2 + 1] = part[ni][1];
            }
        }
        __syncthreads();
        if (wrow == 1 && lane < 4) {
            #pragma unroll
            for (int ni = 0; ni < NT; ++ni) {
                red[wn + ni * 8 + lane * 2]     += part[ni][0];
                red[wn + ni * 8 + lane * 2 + 1] += part[ni][1];
            }
        }
        __syncthreads();
        if (tid < BN)
            aux[(size_t)blockIdx.y * G1Q + bN + tid] = red[tid];
        return;
    }

    // normal epilogue
    float* Df = reinterpret_cast<float*>(Dv)
              + (SPLITK ? (size_t)blockIdx.z * NTOK * N : 0);
    __half* Dh = reinterpret_cast<__half*>(Dv);
    #pragma unroll
    for (int mi = 0; mi < MT; ++mi) {
        const int r0 = bM + wm + mi * 16 + gid;
        #pragma unroll
        for (int ni = 0; ni < NT; ++ni) {
            const int cl = wn + ni * 8 + tig * 2;
            const int c  = bN + cl;
            const float bb0 = HAS_BIAS ? bias[c] : 0.f;
            const float bb1 = HAS_BIAS ? bias[c + 1] : 0.f;
            #pragma unroll
            for (int h = 0; h < 2; ++h) {
                const int r = r0 + h * 8;
                float v0 = acc[mi][ni][2 * h + 0] + bb0;
                float v1 = acc[mi][ni][2 * h + 1] + bb1;
                if (EPI == 1) { v0 = fmaxf(v0, 0.f); v1 = fmaxf(v1, 0.f); }
                if (OUTH) {
                    const int pos = (c & ~15) + ipos16(c & 15);
                    *reinterpret_cast<__half2*>(Dh + (size_t)r * N + pos) =
                        __floats2half2_rn(v0, v1);
                } else {
                    *reinterpret_cast<float2*>(Df + (size_t)r * N + c) = make_float2(v0, v1);
                }
            }
        }
    }
}

// ---------------------------------------------------------------------------
extern "C" void kernel_launch(void* const* d_in, const int* in_sizes, int n_in,
                              void* d_out, int out_size) {
    const float* x       = (const float*)d_in[0];
    const float* gate_w1 = (const float*)d_in[1];
    const float* gate_b1 = (const float*)d_in[2];
    const float* gate_w2 = (const float*)d_in[3];
    const float* gate_b2 = (const float*)d_in[4];
    const float* W1      = (const float*)d_in[5];
    const float* b1      = (const float*)d_in[6];
    const float* W2      = (const float*)d_in[7];
    const float* b2      = (const float*)d_in[8];
    const float* U1      = (const float*)d_in[9];
    const float* SVH1    = (const float*)d_in[10];
    const float* U2      = (const float*)d_in[11];
    const float* SVH2    = (const float*)d_in[12];
    const float* TB1     = (const float*)d_in[13];
    const float* TB2     = (const float*)d_in[14];
    float* out = (float*)d_out;

    float* S = nullptr;
    cudaGetSymbolAddress((void**)&S, g_scratch);
    __half* xc    = (__half*)(S + OFF_XC);
    __half* wg1c  = (__half*)(S + OFF_WG1);
    __half* svh1c = (__half*)(S + OFF_SVH1);
    __half* w1c   = (__half*)(S + OFF_W1);
    __half* u1t   = (__half*)(S + OFF_U1T);
    __half* svh2c = (__half*)(S + OFF_SVH2);
    __half* w2c   = (__half*)(S + OFF_W2);
    __half* u2t   = (__half*)(S + OFF_U2T);
    __half* t1s   = (__half*)(S + OFF_T1S);
    __half* t2s   = (__half*)(S + OFF_T2S);
    __half* hbuf  = (__half*)(S + OFF_H);
    float* t1p   = S + OFF_T1P;
    float* t2p   = S + OFF_T2P;
    float* P8    = S + OFF_P8;
    float* gwv   = S + OFF_GWV;
    float* b1m   = S + OFF_B1M;
    float* b2m   = S + OFF_B2M;

    // router: BM64 BN128, 8 warps (2x4) 32x32, 4 stages, fused mean -> P8
    auto kr = k_mma<64, 128, 2, 4, 4, 3, false, true, false, false, 2>;
    // t partial GEMMs: BM64 BN128, split-K, fp32 raw partials
    auto kt = k_mma<64, 128, 2, 4, 4, 0, false, false, false, true, 2>;
    // fc1: BM128 BN128, 4 warps (2x2) of 64x64, 128 thr, 2 CTA/SM (R9 exact)
    auto k1 = k_mma<128, 128, 2, 2, 4, 1, true, true, true, false, 2>;
    // fc2: same shape, direct (bias + U2 tail in-kernel), fp32 out (R9 exact)
    auto k2 = k_mma<128, 128, 2, 2, 4, 0, true, true, false, false, 2>;

    const int SM_RT = 4 * (64 + 128) * 96;      // 73728
    const int SM_F  = 4 * (128 + 128) * 96;     // 98304
    cudaFuncSetAttribute((const void*)kr, cudaFuncAttributeMaxDynamicSharedMemorySize, SM_RT);
    cudaFuncSetAttribute((const void*)kt, cudaFuncAttributeMaxDynamicSharedMemorySize, SM_RT);
    cudaFuncSetAttribute((const void*)k1, cudaFuncAttributeMaxDynamicSharedMemorySize, SM_F);
    cudaFuncSetAttribute((const void*)k2, cudaFuncAttributeMaxDynamicSharedMemorySize, SM_F);

    // 0: all fp32->fp16(rn) packs with k-permutation, one launch
    PackJobs J;
    J.src[0] = x;       J.dst[0] = (float*)xc;    J.ngroups[0] = NTOK * HQ / 16;
    J.src[1] = gate_w1; J.dst[1] = (float*)wg1c;  J.ngroups[1] = G1Q * HQ / 16;
    J.src[2] = SVH1;    J.dst[2] = (float*)svh1c; J.ngroups[2] = EKQ * HQ / 16;
    J.src[3] = W1;      J.dst[3] = (float*)w1c;   J.ngroups[3] = FQ * HQ / 16;
    J.src[4] = SVH2;    J.dst[4] = (float*)svh2c; J.ngroups[4] = EKQ * FQ / 16;
    J.src[5] = W2;      J.dst[5] = (float*)w2c;   J.ngroups[5] = HQ * FQ / 16;
    k_pack6<<<dim3((NTOK * HQ / 16 + 255) / 256, 6), 256>>>(J);

    // 1: router, fused column-mean -> P8 [128][256]
    kr<<<dim3(G1Q / 128, NTOK / 64), 256, SM_RT>>>(
        xc, wg1c, HQ, nullptr, nullptr, 0, gate_b1, P8, nullptr, G1Q, 0);

    // 2: gw
    k_gwfin<<<BQ, 128>>>(P8, gate_w2, gate_b2, gwv);

    // 3: t1 partials = x @ SVH1^T, K split 2x384
    kt<<<dim3(1, NTOK / 64, 2), 256, SM_RT>>>(
        xc, svh1c, HQ, nullptr, nullptr, 0, nullptr, nullptr, t1p, EKQ, HQ / 2);

    // 4: t1s = fp16(sum_z t1p * gw), permuted
    k_red<2><<<NTOK * 64 / 256, 256>>>(t1p, gwv, t1s);

    // 5,6: transposed low-rank factors -> fp16 permuted
    k_tr_ilv<<<dim3(FQ / 32, 4), dim3(32, 8)>>>(U1, u1t, FQ);
    k_tr_ilv<<<dim3(HQ / 32, 4), dim3(32, 8)>>>(U2, u2t, HQ);

    // 7: merged biases (fp32)
    k_prep<<<(FQ + 255) / 256, 256>>>(b1, TB1, b2, TB2, b1m, b2m);

    // 8: h = fp16(relu(x @ W1^T + t1s @ U1 + b1m))   [8192,3072]
    k1<<<dim3(FQ / 128, NTOK / 128), 128, SM_F>>>(
        xc, w1c, HQ, t1s, u1t, EKQ, b1m, nullptr, hbuf, FQ, 0);

    // 9: t2 partials = h @ SVH2^T, K split 4x768
    kt<<<dim3(1, NTOK / 64, 4), 256, SM_RT>>>(
        hbuf, svh2c, FQ, nullptr, nullptr, 0, nullptr, nullptr, t2p, EKQ, FQ / 4);

    // 10: t2s = fp16(sum_z t2p * gw), permuted
    k_red<4><<<NTOK * 64 / 256, 256>>>(t2p, gwv, t2s);

    // 11: out = h @ W2^T + t2s @ U2 + b2m   [8192,768] fp32
    k2<<<dim3(HQ / 128, NTOK / 128), 128, SM_F>>>(
        hbuf, w2c, FQ, t2s, u2t, EKQ, b2m, nullptr, out, HQ, 0);
}

// round 15
// speedup vs baseline: 1.2180x; 1.0098x over previous
#include <cuda_runtime.h>
#include <cuda_fp16.h>
#include <cstdint>
#include <cstddef>

// ---------------------------------------------------------------------------
// RankOneMoE via fp16 mma.sync.m16n8k16 (fp32 accumulate). fp16 mantissa ==
// tf32 mantissa -> rn-rounded fp16 operands give tf32-grade accuracy.
//   gw[b,ek]  = (sum_s relu(x@gw1^T+b1g))[b,:]@gw2[ek,:]^T /512 + b2g[ek]
//   h         = relu([x | (x@SVH1^T)*gw] @ [W1^T ; U1] + b1m)
//   out       = [h | (h@SVH2^T)*gw] @ [W2^T ; U2] + b2m
// Per-16 k-pair permutation -> fragment = 1 LDS.64; rows padded to 96B.
// R15: fc kernels to 3 CTA/SM (OCC=3, STAGES=3; 3x3=9 stages/SM in flight
//      vs 2x4=8). fc2's 384 CTAs now fit one 444-slot wave -> kills its
//      2-wave quantization without the split-K round-trip that failed twice.
//      Everything else byte-identical to R14 (417.8us record).
// ---------------------------------------------------------------------------

#define BQ   16
#define SQ   512
#define HQ   768
#define FQ   3072
#define EQ   8
#define EKQ  128
#define G1Q  256
#define NTOK (BQ*SQ)      // 8192
#define LAMBDA 0.2f

// ---- scratch layout (float units; fp16 buffers use half the floats) ----
#define OFF_XC    0                         // 8192*768 h
#define OFF_WG1   3145728                   // 256*768 h
#define OFF_SVH1  3244032                   // 128*768 h
#define OFF_W1    3293184                   // 3072*768 h
#define OFF_U1T   4472832                   // 3072*128 h
#define OFF_SVH2  4669440                   // 128*3072 h
#define OFF_W2    4866048                   // 768*3072 h
#define OFF_U2T   6045696                   // 768*128 h
#define OFF_T1S   6094848                   // 8192*128 h
#define OFF_T2S   6619136                   // 8192*128 h
#define OFF_H     7143424                   // 8192*3072 h
#define OFF_T1P   19726336                  // 2*8192*128 f
#define OFF_T2P   21823488                  // 4*8192*128 f
#define OFF_P8    26017792                  // 128*256 f
#define OFF_GWV   26050560                  // 16*128 f
#define OFF_B1M   26052608                  // 3072 f
#define OFF_B2M   26055680                  // 768 f
#define SCRATCH_FLOATS 26056448

static __device__ __align__(256) float g_scratch[SCRATCH_FLOATS];

// ---------------------------- helpers --------------------------------------
__device__ __forceinline__ uint32_t s2u(const void* p) {
    uint32_t a;
    asm("{ .reg .u64 t; cvta.to.shared.u64 t, %1; cvt.u32.u64 %0, t; }" : "=r"(a) : "l"(p));
    return a;
}
// position of original k (0..15) inside the permuted 16-group
__device__ __forceinline__ int ipos16(int k) {
    return (k & 1) + ((k >> 3) & 1) * 2 + (k & 6) * 2;
}
__device__ __forceinline__ void mma16(float* c,
                                      uint32_t a0, uint32_t a1, uint32_t a2, uint32_t a3,
                                      uint32_t b0, uint32_t b1) {
    asm volatile(
        "mma.sync.aligned.m16n8k16.row.col.f32.f16.f16.f32 "
        "{%0,%1,%2,%3},{%4,%5,%6,%7},{%8,%9},{%0,%1,%2,%3};\n"
        : "+f"(c[0]), "+f"(c[1]), "+f"(c[2]), "+f"(c[3])
        : "r"(a0), "r"(a1), "r"(a2), "r"(a3), "r"(b0), "r"(b1));
}

// ---------------------------- pack kernels ---------------------------------
struct PackJobs {
    const float* src[6];
    float*       dst[6];   // fp16 storage viewed as float words
    int          ngroups[6];
};

// fp32 -> fp16(rn) with per-16 k-pair permutation [0,1,8,9,2,3,10,11,...]
__global__ void k_pack6(PackJobs J) {
    const int job = blockIdx.y;
    const int g = blockIdx.x * blockDim.x + threadIdx.x;
    if (g >= J.ngroups[job]) return;
    const float4* s = reinterpret_cast<const float4*>(J.src[job]) + (size_t)g * 4;
    float4 v0 = s[0], v1 = s[1], v2 = s[2], v3 = s[3];
    __half2 h[8];
    h[0] = __floats2half2_rn(v0.x, v0.y);
    h[1] = __floats2half2_rn(v2.x, v2.y);
    h[2] = __floats2half2_rn(v0.z, v0.w);
    h[3] = __floats2half2_rn(v2.z, v2.w);
    h[4] = __floats2half2_rn(v1.x, v1.y);
    h[5] = __floats2half2_rn(v3.x, v3.y);
    h[6] = __floats2half2_rn(v1.z, v1.w);
    h[7] = __floats2half2_rn(v3.z, v3.w);
    float4* d = reinterpret_cast<float4*>(reinterpret_cast<__half*>(J.dst[job]) + (size_t)g * 16);
    d[0] = *reinterpret_cast<float4*>(&h[0]);
    d[1] = *reinterpret_cast<float4*>(&h[4]);
}

// transpose src[128, Ncols] f32 -> dst[Ncols, 128] fp16 permuted
__global__ void k_tr_ilv(const float* __restrict__ S_, __half* __restrict__ Dst, int Ncols) {
    __shared__ float t[32][33];
    const int nx = blockIdx.x * 32, my = blockIdx.y * 32;
    const int x = threadIdx.x, y = threadIdx.y;
    #pragma unroll
    for (int i = 0; i < 32; i += 8)
        t[y + i][x] = S_[(size_t)(my + y + i) * Ncols + nx + x];
    __syncthreads();
    #pragma unroll
    for (int i = 0; i < 32; i += 8) {
        const int r = my + x;
        const int pos = (r & ~15) + ipos16(r & 15);
        Dst[(size_t)(nx + y + i) * 128 + pos] = __float2half_rn(t[x][y + i]);
    }
}

__global__ void k_prep(const float* __restrict__ b1, const float* __restrict__ tb1,
                       const float* __restrict__ b2, const float* __restrict__ tb2,
                       float* __restrict__ b1m, float* __restrict__ b2m) {
    int i = blockIdx.x * blockDim.x + threadIdx.x;
    if (i < FQ) {
        float s = 0.f;
        #pragma unroll
        for (int e = 0; e < EQ; ++e) s += tb1[e * FQ + i];
        b1m[i] = b1[i] + LAMBDA * s;
    }
    if (i < HQ) {
        float s = 0.f;
        #pragma unroll
        for (int e = 0; e < EQ; ++e) s += tb2[e * HQ + i];
        b2m[i] = b2[i] + LAMBDA * s;
    }
}

// gw[b,ek] = dot(P[b,:], w2[ek,:]) / 512 + gb2[ek]   (P8: [128 chunks][256])
__global__ void k_gwfin(const float* __restrict__ P8, const float* __restrict__ w2,
                        const float* __restrict__ gb2, float* __restrict__ gw) {
    __shared__ float Ps[G1Q];
    int b = blockIdx.x, t = threadIdx.x;   // 128 threads
    #pragma unroll
    for (int half = 0; half < 2; ++half) {
        int col = t + half * 128;
        float a = 0.f;
        #pragma unroll
        for (int ch = 0; ch < 8; ++ch) a += P8[(b * 8 + ch) * G1Q + col];
        Ps[col] = a;
    }
    __syncthreads();
    const float* w = w2 + (size_t)t * G1Q;
    float a = 0.f;
    #pragma unroll 8
    for (int g = 0; g < G1Q; ++g) a += w[g] * Ps[g];
    gw[b * EKQ + t] = a * (1.0f / (float)SQ) + gb2[t];
}

// split-K reduce: sum KS partials, scale by gw, convert to fp16 permuted
template<int KS>
__global__ void k_red(const float* __restrict__ tp, const float* __restrict__ gwv,
                      __half* __restrict__ ts) {
    const int idx = blockIdx.x * 256 + threadIdx.x;   // over NTOK*64 pairs
    const int r = idx >> 6, c = (idx & 63) * 2;
    float v0 = tp[(size_t)r * EKQ + c];
    float v1 = tp[(size_t)r * EKQ + c + 1];
    #pragma unroll
    for (int z = 1; z < KS; ++z) {
        v0 += tp[(size_t)z * NTOK * EKQ + (size_t)r * EKQ + c];
        v1 += tp[(size_t)z * NTOK * EKQ + (size_t)r * EKQ + c + 1];
    }
    const int gb = (r >> 9) << 7;
    v0 *= gwv[gb + c]; v1 *= gwv[gb + c + 1];
    const int pos = (c & ~15) + ipos16(c & 15);
    *reinterpret_cast<__half2*>(ts + (size_t)r * EKQ + pos) = __floats2half2_rn(v0, v1);
}

// ---------------------------------------------------------------------------
// Pipelined fp16 mma.sync GEMM. BK=32 per stage, STAGES-deep cp.async.
//   D = epi( A1[M,K1] @ B1[N,K1]^T (+ A2[M,K2] @ B2[N,K2]^T) )
//   EPI: 0=none, 1=relu, 3=router (relu + column-sum over BM rows -> aux).
//   OUTH: fp16 permuted output. SPLITK: z picks kspan window of K1; A2 tail
//   (if HAS2) runs only in the last z; D offset by z*NTOK*N.
// ---------------------------------------------------------------------------
template<int BM, int BN, int WM, int WN, int STAGES, int EPI,
         bool HAS2, bool HAS_BIAS, bool OUTH, bool SPLITK, int OCC>
__global__ void __launch_bounds__(WM * WN * 32, OCC)
k_mma(const __half* __restrict__ A1, const __half* __restrict__ B1, int K1,
      const __half* __restrict__ A2, const __half* __restrict__ B2, int K2,
      const float* __restrict__ bias, float* __restrict__ aux,
      void* __restrict__ Dv, int N, int kspan)
{
    constexpr int THREADS = WM * WN * 32;
    constexpr int WTM = BM / WM, WTN = BN / WN;
    constexpr int MT = WTM / 16, NT = WTN / 8;
    constexpr int RB = 96;                        // padded row bytes (64B data)
    constexpr int STGB = (BM + BN) * RB;
    constexpr int AIT = (BM * 4) / THREADS;
    constexpr int BIT = (BN * 4) / THREADS;

    extern __shared__ char sm[];
    const uint32_t smb = s2u(sm);

    const int tid = threadIdx.x;
    const int wid = tid >> 5, lane = tid & 31;
    const int gid = lane >> 2, tig = lane & 3;
    const int wm = (wid / WN) * WTM;
    const int wn = (wid % WN) * WTN;
    const int bM = blockIdx.y * BM;
    const int bN = blockIdx.x * BN;
    const int kbase = SPLITK ? blockIdx.z * kspan : 0;
    const int T1S = SPLITK ? (kspan >> 5) : (K1 >> 5);
    const bool tail = HAS2 && (!SPLITK || blockIdx.z == gridDim.z - 1);
    const int TS = T1S + (tail ? (K2 >> 5) : 0);

    float acc[MT][NT][4];
    #pragma unroll
    for (int mi = 0; mi < MT; ++mi)
        #pragma unroll
        for (int ni = 0; ni < NT; ++ni)
            #pragma unroll
            for (int j = 0; j < 4; ++j) acc[mi][ni][j] = 0.f;

    auto issue = [&](int jj) {
        const __half* a; const __half* b; int lda, ldb, k0;
        if (!HAS2 || jj < T1S) { a = A1; lda = K1; b = B1; ldb = K1; k0 = kbase + (jj << 5); }
        else                   { a = A2; lda = K2; b = B2; ldb = K2; k0 = (jj - T1S) << 5; }
        const uint32_t sA = smb + (uint32_t)((jj % STAGES) * STGB);
        const uint32_t sB = sA + (uint32_t)BM * RB;
        #pragma unroll
        for (int i = 0; i < AIT; ++i) {
            int idx = tid + i * THREADS; int r = idx >> 2, c = idx & 3;
            const __half* src = a + (size_t)(bM + r) * lda + k0 + c * 8;
            asm volatile("cp.async.cg.shared.global [%0], [%1], 16;\n"
                         :: "r"(sA + (uint32_t)(r * RB + c * 16)), "l"(src) : "memory");
        }
        #pragma unroll
        for (int i = 0; i < BIT; ++i) {
            int idx = tid + i * THREADS; int r = idx >> 2, c = idx & 3;
            const __half* src = b + (size_t)(bN + r) * ldb + k0 + c * 8;
            asm volatile("cp.async.cg.shared.global [%0], [%1], 16;\n"
                         :: "r"(sB + (uint32_t)(r * RB + c * 16)), "l"(src) : "memory");
        }
    };

    #pragma unroll
    for (int s = 0; s < STAGES - 1; ++s) {
        issue(s);
        asm volatile("cp.async.commit_group;\n" ::: "memory");
    }

    for (int j = 0; j < TS; ++j) {
        asm volatile("cp.async.wait_group %0;\n" :: "n"(STAGES - 2) : "memory");
        __syncthreads();

        const char* sst = sm + (j % STAGES) * STGB;
        const char* sA = sst;
        const char* sB = sst + BM * RB;

        #pragma unroll
        for (int g = 0; g < 2; ++g) {
            uint2 fb[NT];
            #pragma unroll
            for (int ni = 0; ni < NT; ++ni)
                fb[ni] = *reinterpret_cast<const uint2*>(
                    sB + (wn + ni * 8 + gid) * RB + g * 32 + tig * 8);

            if (g == 0) {
                if (j + STAGES - 1 < TS) issue(j + STAGES - 1);
                asm volatile("cp.async.commit_group;\n" ::: "memory");
            }

            #pragma unroll
            for (int mi = 0; mi < MT; ++mi) {
                const char* ra = sA + (wm + mi * 16 + gid) * RB + g * 32 + tig * 8;
                const uint2 fa0 = *reinterpret_cast<const uint2*>(ra);
                const uint2 fa1 = *reinterpret_cast<const uint2*>(ra + 8 * RB);
                #pragma unroll
                for (int ni = 0; ni < NT; ++ni)
                    mma16(acc[mi][ni], fa0.x, fa1.x, fa0.y, fa1.y,
                          fb[ni].x, fb[ni].y);
            }
        }
    }

    if (EPI == 3) {
        // router: aux[blockIdx.y][bN + col] = sum_rows relu(acc + bias)
        float part[NT][2];
        #pragma unroll
        for (int ni = 0; ni < NT; ++ni) { part[ni][0] = 0.f; part[ni][1] = 0.f; }
        #pragma unroll
        for (int ni = 0; ni < NT; ++ni) {
            const int cl = wn + ni * 8 + tig * 2;
            const float bb0 = bias[bN + cl], bb1 = bias[bN + cl + 1];
            #pragma unroll
            for (int mi = 0; mi < MT; ++mi)
                #pragma unroll
                for (int h = 0; h < 2; ++h) {
                    part[ni][0] += fmaxf(acc[mi][ni][2 * h + 0] + bb0, 0.f);
                    part[ni][1] += fmaxf(acc[mi][ni][2 * h + 1] + bb1, 0.f);
                }
        }
        #pragma unroll
        for (int ni = 0; ni < NT; ++ni)
            #pragma unroll
            for (int j2 = 0; j2 < 2; ++j2) {
                float v = part[ni][j2];
                v += __shfl_xor_sync(0xffffffffu, v, 4);
                v += __shfl_xor_sync(0xffffffffu, v, 8);
                v += __shfl_xor_sync(0xffffffffu, v, 16);
                part[ni][j2] = v;                        // valid in lanes 0-3
            }
        asm volatile("cp.async.wait_group 0;\n" ::: "memory");
        __syncthreads();
        float* red = reinterpret_cast<float*>(sm);       // reuse stage smem
        if (tid < BN) red[tid] = 0.f;
        __syncthreads();
        const int wrow = wid / WN;                       // WM == 2 assumed
        if (wrow == 0 && lane < 4) {
            #pragma unroll
            for (int ni = 0; ni < NT; ++ni) {
                red[wn + ni * 8 + lane * 2]     = part[ni][0];
                red[wn + ni * 8 + lane * 2 + 1] = part[ni][1];
            }
        }
        __syncthreads();
        if (wrow == 1 && lane < 4) {
            #pragma unroll
            for (int ni = 0; ni < NT; ++ni) {
                red[wn + ni * 8 + lane * 2]     += part[ni][0];
                red[wn + ni * 8 + lane * 2 + 1] += part[ni][1];
            }
        }
        __syncthreads();
        if (tid < BN)
            aux[(size_t)blockIdx.y * G1Q + bN + tid] = red[tid];
        return;
    }

    // normal epilogue
    float* Df = reinterpret_cast<float*>(Dv)
              + (SPLITK ? (size_t)blockIdx.z * NTOK * N : 0);
    __half* Dh = reinterpret_cast<__half*>(Dv);
    #pragma unroll
    for (int mi = 0; mi < MT; ++mi) {
        const int r0 = bM + wm + mi * 16 + gid;
        #pragma unroll
        for (int ni = 0; ni < NT; ++ni) {
            const int cl = wn + ni * 8 + tig * 2;
            const int c  = bN + cl;
            const float bb0 = HAS_BIAS ? bias[c] : 0.f;
            const float bb1 = HAS_BIAS ? bias[c + 1] : 0.f;
            #pragma unroll
            for (int h = 0; h < 2; ++h) {
                const int r = r0 + h * 8;
                float v0 = acc[mi][ni][2 * h + 0] + bb0;
                float v1 = acc[mi][ni][2 * h + 1] + bb1;
                if (EPI == 1) { v0 = fmaxf(v0, 0.f); v1 = fmaxf(v1, 0.f); }
                if (OUTH) {
                    const int pos = (c & ~15) + ipos16(c & 15);
                    *reinterpret_cast<__half2*>(Dh + (size_t)r * N + pos) =
                        __floats2half2_rn(v0, v1);
                } else {
                    *reinterpret_cast<float2*>(Df + (size_t)r * N + c) = make_float2(v0, v1);
                }
            }
        }
    }
}

// ---------------------------------------------------------------------------
extern "C" void kernel_launch(void* const* d_in, const int* in_sizes, int n_in,
                              void* d_out, int out_size) {
    const float* x       = (const float*)d_in[0];
    const float* gate_w1 = (const float*)d_in[1];
    const float* gate_b1 = (const float*)d_in[2];
    const float* gate_w2 = (const float*)d_in[3];
    const float* gate_b2 = (const float*)d_in[4];
    const float* W1      = (const float*)d_in[5];
    const float* b1      = (const float*)d_in[6];
    const float* W2      = (const float*)d_in[7];
    const float* b2      = (const float*)d_in[8];
    const float* U1      = (const float*)d_in[9];
    const float* SVH1    = (const float*)d_in[10];
    const float* U2      = (const float*)d_in[11];
    const float* SVH2    = (const float*)d_in[12];
    const float* TB1     = (const float*)d_in[13];
    const float* TB2     = (const float*)d_in[14];
    float* out = (float*)d_out;

    float* S = nullptr;
    cudaGetSymbolAddress((void**)&S, g_scratch);
    __half* xc    = (__half*)(S + OFF_XC);
    __half* wg1c  = (__half*)(S + OFF_WG1);
    __half* svh1c = (__half*)(S + OFF_SVH1);
    __half* w1c   = (__half*)(S + OFF_W1);
    __half* u1t   = (__half*)(S + OFF_U1T);
    __half* svh2c = (__half*)(S + OFF_SVH2);
    __half* w2c   = (__half*)(S + OFF_W2);
    __half* u2t   = (__half*)(S + OFF_U2T);
    __half* t1s   = (__half*)(S + OFF_T1S);
    __half* t2s   = (__half*)(S + OFF_T2S);
    __half* hbuf  = (__half*)(S + OFF_H);
    float* t1p   = S + OFF_T1P;
    float* t2p   = S + OFF_T2P;
    float* P8    = S + OFF_P8;
    float* gwv   = S + OFF_GWV;
    float* b1m   = S + OFF_B1M;
    float* b2m   = S + OFF_B2M;

    // router: BM64 BN128, 8 warps (2x4) 32x32, 4 stages, fused mean -> P8
    auto kr = k_mma<64, 128, 2, 4, 4, 3, false, true, false, false, 2>;
    // t partial GEMMs: BM64 BN128, split-K, fp32 raw partials
    auto kt = k_mma<64, 128, 2, 4, 4, 0, false, false, false, true, 2>;
    // fc1: BM128 BN128, 4 warps (2x2) of 64x64, 3 stages, 3 CTA/SM
    auto k1 = k_mma<128, 128, 2, 2, 3, 1, true, true, true, false, 3>;
    // fc2: same shape, direct (bias + U2 tail in-kernel), 3 CTA/SM -> 1 wave
    auto k2 = k_mma<128, 128, 2, 2, 3, 0, true, true, false, false, 3>;

    const int SM_RT = 4 * (64 + 128) * 96;      // 73728
    const int SM_F  = 3 * (128 + 128) * 96;     // 73728 (3 stages)
    cudaFuncSetAttribute((const void*)kr, cudaFuncAttributeMaxDynamicSharedMemorySize, SM_RT);
    cudaFuncSetAttribute((const void*)kt, cudaFuncAttributeMaxDynamicSharedMemorySize, SM_RT);
    cudaFuncSetAttribute((const void*)k1, cudaFuncAttributeMaxDynamicSharedMemorySize, SM_F);
    cudaFuncSetAttribute((const void*)k2, cudaFuncAttributeMaxDynamicSharedMemorySize, SM_F);

    // 0: all fp32->fp16(rn) packs with k-permutation, one launch
    PackJobs J;
    J.src[0] = x;       J.dst[0] = (float*)xc;    J.ngroups[0] = NTOK * HQ / 16;
    J.src[1] = gate_w1; J.dst[1] = (float*)wg1c;  J.ngroups[1] = G1Q * HQ / 16;
    J.src[2] = SVH1;    J.dst[2] = (float*)svh1c; J.ngroups[2] = EKQ * HQ / 16;
    J.src[3] = W1;      J.dst[3] = (float*)w1c;   J.ngroups[3] = FQ * HQ / 16;
    J.src[4] = SVH2;    J.dst[4] = (float*)svh2c; J.ngroups[4] = EKQ * FQ / 16;
    J.src[5] = W2;      J.dst[5] = (float*)w2c;   J.ngroups[5] = HQ * FQ / 16;
    k_pack6<<<dim3((NTOK * HQ / 16 + 255) / 256, 6), 256>>>(J);

    // 1: router, fused column-mean -> P8 [128][256]
    kr<<<dim3(G1Q / 128, NTOK / 64), 256, SM_RT>>>(
        xc, wg1c, HQ, nullptr, nullptr, 0, gate_b1, P8, nullptr, G1Q, 0);

    // 2: gw
    k_gwfin<<<BQ, 128>>>(P8, gate_w2, gate_b2, gwv);

    // 3: t1 partials = x @ SVH1^T, K split 2x384
    kt<<<dim3(1, NTOK / 64, 2), 256, SM_RT>>>(
        xc, svh1c, HQ, nullptr, nullptr, 0, nullptr, nullptr, t1p, EKQ, HQ / 2);

    // 4: t1s = fp16(sum_z t1p * gw), permuted
    k_red<2><<<NTOK * 64 / 256, 256>>>(t1p, gwv, t1s);

    // 5,6: transposed low-rank factors -> fp16 permuted
    k_tr_ilv<<<dim3(FQ / 32, 4), dim3(32, 8)>>>(U1, u1t, FQ);
    k_tr_ilv<<<dim3(HQ / 32, 4), dim3(32, 8)>>>(U2, u2t, HQ);

    // 7: merged biases (fp32)
    k_prep<<<(FQ + 255) / 256, 256>>>(b1, TB1, b2, TB2, b1m, b2m);

    // 8: h = fp16(relu(x @ W1^T + t1s @ U1 + b1m))   [8192,3072]
    k1<<<dim3(FQ / 128, NTOK / 128), 128, SM_F>>>(
        xc, w1c, HQ, t1s, u1t, EKQ, b1m, nullptr, hbuf, FQ, 0);

    // 9: t2 partials = h @ SVH2^T, K split 4x768
    kt<<<dim3(1, NTOK / 64, 4), 256, SM_RT>>>(
        hbuf, svh2c, FQ, nullptr, nullptr, 0, nullptr, nullptr, t2p, EKQ, FQ / 4);

    // 10: t2s = fp16(sum_z t2p * gw), permuted
    k_red<4><<<NTOK * 64 / 256, 256>>>(t2p, gwv, t2s);

    // 11: out = h @ W2^T + t2s @ U2 + b2m   [8192,768] fp32
    k2<<<dim3(HQ / 128, NTOK / 128), 128, SM_F>>>(
        hbuf, w2c, FQ, t2s, u2t, EKQ, b2m, nullptr, out, HQ, 0);
}

// round 16
// speedup vs baseline: 1.2250x; 1.0058x over previous
#include <cuda_runtime.h>
#include <cuda_fp16.h>
#include <cstdint>
#include <cstddef>

// ---------------------------------------------------------------------------
// RankOneMoE via fp16 mma.sync.m16n8k16 (fp32 accumulate). fp16 mantissa ==
// tf32 mantissa -> rn-rounded fp16 operands give tf32-grade accuracy.
//   gw[b,ek]  = (sum_s relu(x@gw1^T+b1g))[b,:]@gw2[ek,:]^T /512 + b2g[ek]
//   h         = relu([x | (x@SVH1^T)*gw] @ [W1^T ; U1] + b1m)
//   out       = [h | (h@SVH2^T)*gw] @ [W2^T ; U2] + b2m
// Per-16 k-pair permutation -> fragment = 1 LDS.64; rows padded to 96B.
// R16: per-kernel wave-aware occupancy. fc1 back to 2 CTA x 4 stages (3.46
//      waves either way -> keep deeper pipeline); fc2 stays 3 CTA x 3 stages
//      (single 444-slot wave, the R15 win); t kernels to 3 CTA x 3 stages
//      (t2's 512 CTAs: 1.73 -> 1.15 waves).
// ---------------------------------------------------------------------------

#define BQ   16
#define SQ   512
#define HQ   768
#define FQ   3072
#define EQ   8
#define EKQ  128
#define G1Q  256
#define NTOK (BQ*SQ)      // 8192
#define LAMBDA 0.2f

// ---- scratch layout (float units; fp16 buffers use half the floats) ----
#define OFF_XC    0                         // 8192*768 h
#define OFF_WG1   3145728                   // 256*768 h
#define OFF_SVH1  3244032                   // 128*768 h
#define OFF_W1    3293184                   // 3072*768 h
#define OFF_U1T   4472832                   // 3072*128 h
#define OFF_SVH2  4669440                   // 128*3072 h
#define OFF_W2    4866048                   // 768*3072 h
#define OFF_U2T   6045696                   // 768*128 h
#define OFF_T1S   6094848                   // 8192*128 h
#define OFF_T2S   6619136                   // 8192*128 h
#define OFF_H     7143424                   // 8192*3072 h
#define OFF_T1P   19726336                  // 2*8192*128 f
#define OFF_T2P   21823488                  // 4*8192*128 f
#define OFF_P8    26017792                  // 128*256 f
#define OFF_GWV   26050560                  // 16*128 f
#define OFF_B1M   26052608                  // 3072 f
#define OFF_B2M   26055680                  // 768 f
#define SCRATCH_FLOATS 26056448

static __device__ __align__(256) float g_scratch[SCRATCH_FLOATS];

// ---------------------------- helpers --------------------------------------
__device__ __forceinline__ uint32_t s2u(const void* p) {
    uint32_t a;
    asm("{ .reg .u64 t; cvta.to.shared.u64 t, %1; cvt.u32.u64 %0, t; }" : "=r"(a) : "l"(p));
    return a;
}
// position of original k (0..15) inside the permuted 16-group
__device__ __forceinline__ int ipos16(int k) {
    return (k & 1) + ((k >> 3) & 1) * 2 + (k & 6) * 2;
}
__device__ __forceinline__ void mma16(float* c,
                                      uint32_t a0, uint32_t a1, uint32_t a2, uint32_t a3,
                                      uint32_t b0, uint32_t b1) {
    asm volatile(
        "mma.sync.aligned.m16n8k16.row.col.f32.f16.f16.f32 "
        "{%0,%1,%2,%3},{%4,%5,%6,%7},{%8,%9},{%0,%1,%2,%3};\n"
        : "+f"(c[0]), "+f"(c[1]), "+f"(c[2]), "+f"(c[3])
        : "r"(a0), "r"(a1), "r"(a2), "r"(a3), "r"(b0), "r"(b1));
}

// ---------------------------- pack kernels ---------------------------------
struct PackJobs {
    const float* src[6];
    float*       dst[6];   // fp16 storage viewed as float words
    int          ngroups[6];
};

// fp32 -> fp16(rn) with per-16 k-pair permutation [0,1,8,9,2,3,10,11,...]
__global__ void k_pack6(PackJobs J) {
    const int job = blockIdx.y;
    const int g = blockIdx.x * blockDim.x + threadIdx.x;
    if (g >= J.ngroups[job]) return;
    const float4* s = reinterpret_cast<const float4*>(J.src[job]) + (size_t)g * 4;
    float4 v0 = s[0], v1 = s[1], v2 = s[2], v3 = s[3];
    __half2 h[8];
    h[0] = __floats2half2_rn(v0.x, v0.y);
    h[1] = __floats2half2_rn(v2.x, v2.y);
    h[2] = __floats2half2_rn(v0.z, v0.w);
    h[3] = __floats2half2_rn(v2.z, v2.w);
    h[4] = __floats2half2_rn(v1.x, v1.y);
    h[5] = __floats2half2_rn(v3.x, v3.y);
    h[6] = __floats2half2_rn(v1.z, v1.w);
    h[7] = __floats2half2_rn(v3.z, v3.w);
    float4* d = reinterpret_cast<float4*>(reinterpret_cast<__half*>(J.dst[job]) + (size_t)g * 16);
    d[0] = *reinterpret_cast<float4*>(&h[0]);
    d[1] = *reinterpret_cast<float4*>(&h[4]);
}

// transpose src[128, Ncols] f32 -> dst[Ncols, 128] fp16 permuted
__global__ void k_tr_ilv(const float* __restrict__ S_, __half* __restrict__ Dst, int Ncols) {
    __shared__ float t[32][33];
    const int nx = blockIdx.x * 32, my = blockIdx.y * 32;
    const int x = threadIdx.x, y = threadIdx.y;
    #pragma unroll
    for (int i = 0; i < 32; i += 8)
        t[y + i][x] = S_[(size_t)(my + y + i) * Ncols + nx + x];
    __syncthreads();
    #pragma unroll
    for (int i = 0; i < 32; i += 8) {
        const int r = my + x;
        const int pos = (r & ~15) + ipos16(r & 15);
        Dst[(size_t)(nx + y + i) * 128 + pos] = __float2half_rn(t[x][y + i]);
    }
}

__global__ void k_prep(const float* __restrict__ b1, const float* __restrict__ tb1,
                       const float* __restrict__ b2, const float* __restrict__ tb2,
                       float* __restrict__ b1m, float* __restrict__ b2m) {
    int i = blockIdx.x * blockDim.x + threadIdx.x;
    if (i < FQ) {
        float s = 0.f;
        #pragma unroll
        for (int e = 0; e < EQ; ++e) s += tb1[e * FQ + i];
        b1m[i] = b1[i] + LAMBDA * s;
    }
    if (i < HQ) {
        float s = 0.f;
        #pragma unroll
        for (int e = 0; e < EQ; ++e) s += tb2[e * HQ + i];
        b2m[i] = b2[i] + LAMBDA * s;
    }
}

// gw[b,ek] = dot(P[b,:], w2[ek,:]) / 512 + gb2[ek]   (P8: [128 chunks][256])
__global__ void k_gwfin(const float* __restrict__ P8, const float* __restrict__ w2,
                        const float* __restrict__ gb2, float* __restrict__ gw) {
    __shared__ float Ps[G1Q];
    int b = blockIdx.x, t = threadIdx.x;   // 128 threads
    #pragma unroll
    for (int half = 0; half < 2; ++half) {
        int col = t + half * 128;
        float a = 0.f;
        #pragma unroll
        for (int ch = 0; ch < 8; ++ch) a += P8[(b * 8 + ch) * G1Q + col];
        Ps[col] = a;
    }
    __syncthreads();
    const float* w = w2 + (size_t)t * G1Q;
    float a = 0.f;
    #pragma unroll 8
    for (int g = 0; g < G1Q; ++g) a += w[g] * Ps[g];
    gw[b * EKQ + t] = a * (1.0f / (float)SQ) + gb2[t];
}

// split-K reduce: sum KS partials, scale by gw, convert to fp16 permuted
template<int KS>
__global__ void k_red(const float* __restrict__ tp, const float* __restrict__ gwv,
                      __half* __restrict__ ts) {
    const int idx = blockIdx.x * 256 + threadIdx.x;   // over NTOK*64 pairs
    const int r = idx >> 6, c = (idx & 63) * 2;
    float v0 = tp[(size_t)r * EKQ + c];
    float v1 = tp[(size_t)r * EKQ + c + 1];
    #pragma unroll
    for (int z = 1; z < KS; ++z) {
        v0 += tp[(size_t)z * NTOK * EKQ + (size_t)r * EKQ + c];
        v1 += tp[(size_t)z * NTOK * EKQ + (size_t)r * EKQ + c + 1];
    }
    const int gb = (r >> 9) << 7;
    v0 *= gwv[gb + c]; v1 *= gwv[gb + c + 1];
    const int pos = (c & ~15) + ipos16(c & 15);
    *reinterpret_cast<__half2*>(ts + (size_t)r * EKQ + pos) = __floats2half2_rn(v0, v1);
}

// ---------------------------------------------------------------------------
// Pipelined fp16 mma.sync GEMM. BK=32 per stage, STAGES-deep cp.async.
//   D = epi( A1[M,K1] @ B1[N,K1]^T (+ A2[M,K2] @ B2[N,K2]^T) )
//   EPI: 0=none, 1=relu, 3=router (relu + column-sum over BM rows -> aux).
//   OUTH: fp16 permuted output. SPLITK: z picks kspan window of K1; A2 tail
//   (if HAS2) runs only in the last z; D offset by z*NTOK*N.
// ---------------------------------------------------------------------------
template<int BM, int BN, int WM, int WN, int STAGES, int EPI,
         bool HAS2, bool HAS_BIAS, bool OUTH, bool SPLITK, int OCC>
__global__ void __launch_bounds__(WM * WN * 32, OCC)
k_mma(const __half* __restrict__ A1, const __half* __restrict__ B1, int K1,
      const __half* __restrict__ A2, const __half* __restrict__ B2, int K2,
      const float* __restrict__ bias, float* __restrict__ aux,
      void* __restrict__ Dv, int N, int kspan)
{
    constexpr int THREADS = WM * WN * 32;
    constexpr int WTM = BM / WM, WTN = BN / WN;
    constexpr int MT = WTM / 16, NT = WTN / 8;
    constexpr int RB = 96;                        // padded row bytes (64B data)
    constexpr int STGB = (BM + BN) * RB;
    constexpr int AIT = (BM * 4) / THREADS;
    constexpr int BIT = (BN * 4) / THREADS;

    extern __shared__ char sm[];
    const uint32_t smb = s2u(sm);

    const int tid = threadIdx.x;
    const int wid = tid >> 5, lane = tid & 31;
    const int gid = lane >> 2, tig = lane & 3;
    const int wm = (wid / WN) * WTM;
    const int wn = (wid % WN) * WTN;
    const int bM = blockIdx.y * BM;
    const int bN = blockIdx.x * BN;
    const int kbase = SPLITK ? blockIdx.z * kspan : 0;
    const int T1S = SPLITK ? (kspan >> 5) : (K1 >> 5);
    const bool tail = HAS2 && (!SPLITK || blockIdx.z == gridDim.z - 1);
    const int TS = T1S + (tail ? (K2 >> 5) : 0);

    float acc[MT][NT][4];
    #pragma unroll
    for (int mi = 0; mi < MT; ++mi)
        #pragma unroll
        for (int ni = 0; ni < NT; ++ni)
            #pragma unroll
            for (int j = 0; j < 4; ++j) acc[mi][ni][j] = 0.f;

    auto issue = [&](int jj) {
        const __half* a; const __half* b; int lda, ldb, k0;
        if (!HAS2 || jj < T1S) { a = A1; lda = K1; b = B1; ldb = K1; k0 = kbase + (jj << 5); }
        else                   { a = A2; lda = K2; b = B2; ldb = K2; k0 = (jj - T1S) << 5; }
        const uint32_t sA = smb + (uint32_t)((jj % STAGES) * STGB);
        const uint32_t sB = sA + (uint32_t)BM * RB;
        #pragma unroll
        for (int i = 0; i < AIT; ++i) {
            int idx = tid + i * THREADS; int r = idx >> 2, c = idx & 3;
            const __half* src = a + (size_t)(bM + r) * lda + k0 + c * 8;
            asm volatile("cp.async.cg.shared.global [%0], [%1], 16;\n"
                         :: "r"(sA + (uint32_t)(r * RB + c * 16)), "l"(src) : "memory");
        }
        #pragma unroll
        for (int i = 0; i < BIT; ++i) {
            int idx = tid + i * THREADS; int r = idx >> 2, c = idx & 3;
            const __half* src = b + (size_t)(bN + r) * ldb + k0 + c * 8;
            asm volatile("cp.async.cg.shared.global [%0], [%1], 16;\n"
                         :: "r"(sB + (uint32_t)(r * RB + c * 16)), "l"(src) : "memory");
        }
    };

    #pragma unroll
    for (int s = 0; s < STAGES - 1; ++s) {
        issue(s);
        asm volatile("cp.async.commit_group;\n" ::: "memory");
    }

    for (int j = 0; j < TS; ++j) {
        asm volatile("cp.async.wait_group %0;\n" :: "n"(STAGES - 2) : "memory");
        __syncthreads();

        const char* sst = sm + (j % STAGES) * STGB;
        const char* sA = sst;
        const char* sB = sst + BM * RB;

        #pragma unroll
        for (int g = 0; g < 2; ++g) {
            uint2 fb[NT];
            #pragma unroll
            for (int ni = 0; ni < NT; ++ni)
                fb[ni] = *reinterpret_cast<const uint2*>(
                    sB + (wn + ni * 8 + gid) * RB + g * 32 + tig * 8);

            if (g == 0) {
                if (j + STAGES - 1 < TS) issue(j + STAGES - 1);
                asm volatile("cp.async.commit_group;\n" ::: "memory");
            }

            #pragma unroll
            for (int mi = 0; mi < MT; ++mi) {
                const char* ra = sA + (wm + mi * 16 + gid) * RB + g * 32 + tig * 8;
                const uint2 fa0 = *reinterpret_cast<const uint2*>(ra);
                const uint2 fa1 = *reinterpret_cast<const uint2*>(ra + 8 * RB);
                #pragma unroll
                for (int ni = 0; ni < NT; ++ni)
                    mma16(acc[mi][ni], fa0.x, fa1.x, fa0.y, fa1.y,
                          fb[ni].x, fb[ni].y);
            }
        }
    }

    if (EPI == 3) {
        // router: aux[blockIdx.y][bN + col] = sum_rows relu(acc + bias)
        float part[NT][2];
        #pragma unroll
        for (int ni = 0; ni < NT; ++ni) { part[ni][0] = 0.f; part[ni][1] = 0.f; }
        #pragma unroll
        for (int ni = 0; ni < NT; ++ni) {
            const int cl = wn + ni * 8 + tig * 2;
            const float bb0 = bias[bN + cl], bb1 = bias[bN + cl + 1];
            #pragma unroll
            for (int mi = 0; mi < MT; ++mi)
                #pragma unroll
                for (int h = 0; h < 2; ++h) {
                    part[ni][0] += fmaxf(acc[mi][ni][2 * h + 0] + bb0, 0.f);
                    part[ni][1] += fmaxf(acc[mi][ni][2 * h + 1] + bb1, 0.f);
                }
        }
        #pragma unroll
        for (int ni = 0; ni < NT; ++ni)
            #pragma unroll
            for (int j2 = 0; j2 < 2; ++j2) {
                float v = part[ni][j2];
                v += __shfl_xor_sync(0xffffffffu, v, 4);
                v += __shfl_xor_sync(0xffffffffu, v, 8);
                v += __shfl_xor_sync(0xffffffffu, v, 16);
                part[ni][j2] = v;                        // valid in lanes 0-3
            }
        asm volatile("cp.async.wait_group 0;\n" ::: "memory");
        __syncthreads();
        float* red = reinterpret_cast<float*>(sm);       // reuse stage smem
        if (tid < BN) red[tid] = 0.f;
        __syncthreads();
        const int wrow = wid / WN;                       // WM == 2 assumed
        if (wrow == 0 && lane < 4) {
            #pragma unroll
            for (int ni = 0; ni < NT; ++ni) {
                red[wn + ni * 8 + lane * 2]     = part[ni][0];
                red[wn + ni * 8 + lane * 2 + 1] = part[ni][1];
            }
        }
        __syncthreads();
        if (wrow == 1 && lane < 4) {
            #pragma unroll
            for (int ni = 0; ni < NT; ++ni) {
                red[wn + ni * 8 + lane * 2]     += part[ni][0];
                red[wn + ni * 8 + lane * 2 + 1] += part[ni][1];
            }
        }
        __syncthreads();
        if (tid < BN)
            aux[(size_t)blockIdx.y * G1Q + bN + tid] = red[tid];
        return;
    }

    // normal epilogue
    float* Df = reinterpret_cast<float*>(Dv)
              + (SPLITK ? (size_t)blockIdx.z * NTOK * N : 0);
    __half* Dh = reinterpret_cast<__half*>(Dv);
    #pragma unroll
    for (int mi = 0; mi < MT; ++mi) {
        const int r0 = bM + wm + mi * 16 + gid;
        #pragma unroll
        for (int ni = 0; ni < NT; ++ni) {
            const int cl = wn + ni * 8 + tig * 2;
            const int c  = bN + cl;
            const float bb0 = HAS_BIAS ? bias[c] : 0.f;
            const float bb1 = HAS_BIAS ? bias[c + 1] : 0.f;
            #pragma unroll
            for (int h = 0; h < 2; ++h) {
                const int r = r0 + h * 8;
                float v0 = acc[mi][ni][2 * h + 0] + bb0;
                float v1 = acc[mi][ni][2 * h + 1] + bb1;
                if (EPI == 1) { v0 = fmaxf(v0, 0.f); v1 = fmaxf(v1, 0.f); }
                if (OUTH) {
                    const int pos = (c & ~15) + ipos16(c & 15);
                    *reinterpret_cast<__half2*>(Dh + (size_t)r * N + pos) =
                        __floats2half2_rn(v0, v1);
                } else {
                    *reinterpret_cast<float2*>(Df + (size_t)r * N + c) = make_float2(v0, v1);
                }
            }
        }
    }
}

// ---------------------------------------------------------------------------
extern "C" void kernel_launch(void* const* d_in, const int* in_sizes, int n_in,
                              void* d_out, int out_size) {
    const float* x       = (const float*)d_in[0];
    const float* gate_w1 = (const float*)d_in[1];
    const float* gate_b1 = (const float*)d_in[2];
    const float* gate_w2 = (const float*)d_in[3];
    const float* gate_b2 = (const float*)d_in[4];
    const float* W1      = (const float*)d_in[5];
    const float* b1      = (const float*)d_in[6];
    const float* W2      = (const float*)d_in[7];
    const float* b2      = (const float*)d_in[8];
    const float* U1      = (const float*)d_in[9];
    const float* SVH1    = (const float*)d_in[10];
    const float* U2      = (const float*)d_in[11];
    const float* SVH2    = (const float*)d_in[12];
    const float* TB1     = (const float*)d_in[13];
    const float* TB2     = (const float*)d_in[14];
    float* out = (float*)d_out;

    float* S = nullptr;
    cudaGetSymbolAddress((void**)&S, g_scratch);
    __half* xc    = (__half*)(S + OFF_XC);
    __half* wg1c  = (__half*)(S + OFF_WG1);
    __half* svh1c = (__half*)(S + OFF_SVH1);
    __half* w1c   = (__half*)(S + OFF_W1);
    __half* u1t   = (__half*)(S + OFF_U1T);
    __half* svh2c = (__half*)(S + OFF_SVH2);
    __half* w2c   = (__half*)(S + OFF_W2);
    __half* u2t   = (__half*)(S + OFF_U2T);
    __half* t1s   = (__half*)(S + OFF_T1S);
    __half* t2s   = (__half*)(S + OFF_T2S);
    __half* hbuf  = (__half*)(S + OFF_H);
    float* t1p   = S + OFF_T1P;
    float* t2p   = S + OFF_T2P;
    float* P8    = S + OFF_P8;
    float* gwv   = S + OFF_GWV;
    float* b1m   = S + OFF_B1M;
    float* b2m   = S + OFF_B2M;

    // router: BM64 BN128, 8 warps (2x4) 32x32, 4 stages, 2 CTA/SM, fused mean
    auto kr = k_mma<64, 128, 2, 4, 4, 3, false, true, false, false, 2>;
    // t partial GEMMs: BM64 BN128, split-K, 3 stages, 3 CTA/SM (t2 -> 1.15 waves)
    auto kt = k_mma<64, 128, 2, 4, 3, 0, false, false, false, true, 3>;
    // fc1: BM128 BN128, 4 warps (2x2) of 64x64, 4 stages, 2 CTA/SM (R14 best)
    auto k1 = k_mma<128, 128, 2, 2, 4, 1, true, true, true, false, 2>;
    // fc2: same shape, 3 stages, 3 CTA/SM -> single wave (R15 win)
    auto k2 = k_mma<128, 128, 2, 2, 3, 0, true, true, false, false, 3>;

    const int SM_R  = 4 * (64 + 128) * 96;      // 73728
    const int SM_T  = 3 * (64 + 128) * 96;      // 55296 (3 stages)
    const int SM_F1 = 4 * (128 + 128) * 96;     // 98304 (4 stages)
    const int SM_F2 = 3 * (128 + 128) * 96;     // 73728 (3 stages)
    cudaFuncSetAttribute((const void*)kr, cudaFuncAttributeMaxDynamicSharedMemorySize, SM_R);
    cudaFuncSetAttribute((const void*)kt, cudaFuncAttributeMaxDynamicSharedMemorySize, SM_T);
    cudaFuncSetAttribute((const void*)k1, cudaFuncAttributeMaxDynamicSharedMemorySize, SM_F1);
    cudaFuncSetAttribute((const void*)k2, cudaFuncAttributeMaxDynamicSharedMemorySize, SM_F2);

    // 0: all fp32->fp16(rn) packs with k-permutation, one launch
    PackJobs J;
    J.src[0] = x;       J.dst[0] = (float*)xc;    J.ngroups[0] = NTOK * HQ / 16;
    J.src[1] = gate_w1; J.dst[1] = (float*)wg1c;  J.ngroups[1] = G1Q * HQ / 16;
    J.src[2] = SVH1;    J.dst[2] = (float*)svh1c; J.ngroups[2] = EKQ * HQ / 16;
    J.src[3] = W1;      J.dst[3] = (float*)w1c;   J.ngroups[3] = FQ * HQ / 16;
    J.src[4] = SVH2;    J.dst[4] = (float*)svh2c; J.ngroups[4] = EKQ * FQ / 16;
    J.src[5] = W2;      J.dst[5] = (float*)w2c;   J.ngroups[5] = HQ * FQ / 16;
    k_pack6<<<dim3((NTOK * HQ / 16 + 255) / 256, 6), 256>>>(J);

    // 1: router, fused column-mean -> P8 [128][256]
    kr<<<dim3(G1Q / 128, NTOK / 64), 256, SM_R>>>(
        xc, wg1c, HQ, nullptr, nullptr, 0, gate_b1, P8, nullptr, G1Q, 0);

    // 2: gw
    k_gwfin<<<BQ, 128>>>(P8, gate_w2, gate_b2, gwv);

    // 3: t1 partials = x @ SVH1^T, K split 2x384
    kt<<<dim3(1, NTOK / 64, 2), 256, SM_T>>>(
        xc, svh1c, HQ, nullptr, nullptr, 0, nullptr, nullptr, t1p, EKQ, HQ / 2);

    // 4: t1s = fp16(sum_z t1p * gw), permuted
    k_red<2><<<NTOK * 64 / 256, 256>>>(t1p, gwv, t1s);

    // 5,6: transposed low-rank factors -> fp16 permuted
    k_tr_ilv<<<dim3(FQ / 32, 4), dim3(32, 8)>>>(U1, u1t, FQ);
    k_tr_ilv<<<dim3(HQ / 32, 4), dim3(32, 8)>>>(U2, u2t, HQ);

    // 7: merged biases (fp32)
    k_prep<<<(FQ + 255) / 256, 256>>>(b1, TB1, b2, TB2, b1m, b2m);

    // 8: h = fp16(relu(x @ W1^T + t1s @ U1 + b1m))   [8192,3072]
    k1<<<dim3(FQ / 128, NTOK / 128), 128, SM_F1>>>(
        xc, w1c, HQ, t1s, u1t, EKQ, b1m, nullptr, hbuf, FQ, 0);

    // 9: t2 partials = h @ SVH2^T, K split 4x768
    kt<<<dim3(1, NTOK / 64, 4), 256, SM_T>>>(
        hbuf, svh2c, FQ, nullptr, nullptr, 0, nullptr, nullptr, t2p, EKQ, FQ / 4);

    // 10: t2s = fp16(sum_z t2p * gw), permuted
    k_red<4><<<NTOK * 64 / 256, 256>>>(t2p, gwv, t2s);

    // 11: out = h @ W2^T + t2s @ U2 + b2m   [8192,768] fp32
    k2<<<dim3(HQ / 128, NTOK / 128), 128, SM_F2>>>(
        hbuf, w2c, FQ, t2s, u2t, EKQ, b2m, nullptr, out, HQ, 0);
}